// round 10
// baseline (speedup 1.0000x reference)
#include <cuda_runtime.h>
#include <cuda_bf16.h>
#include <cstdint>
#include <math.h>

#define BB 4
#define SS 2048
#define DD 1024
#define HH 16
#define DHH 64
#define MM (BB*SS)

typedef __nv_bfloat16 bf16;

// ---------------- device scratch (allocation-free rule) ----------------
__device__ bf16  g_xb[(size_t)MM*DD];      // x in bf16 [m][k]
__device__ bf16  g_wq[DD*DD];              // W^T bf16 [n][k]
__device__ bf16  g_wk[DD*DD];
__device__ bf16  g_wv[DD*DD];
__device__ bf16  g_wo[DD*DD];
__device__ bf16  g_q [(size_t)MM*DD];      // [b,h,s,d]
__device__ bf16  g_k [(size_t)MM*DD];      // [b,h,s,d]
__device__ bf16  g_vt[(size_t)MM*DD];      // [b,h,d,s]  (transposed for PV)
__device__ bf16  g_ctx[(size_t)MM*DD];     // [m][n]
__device__ float g_y [(size_t)MM*DD];      // pre-LN fp32

// ---------------- helpers ----------------
__device__ __forceinline__ void cp16(unsigned dst, const void* src) {
    asm volatile("cp.async.cg.shared.global [%0], [%1], 16;\n" :: "r"(dst), "l"(src));
}
__device__ __forceinline__ void cp_commit() { asm volatile("cp.async.commit_group;\n"); }
template<int N> __device__ __forceinline__ void cp_wait() {
    asm volatile("cp.async.wait_group %0;\n" :: "n"(N));
}
__device__ __forceinline__ void mma16816(float* d, const unsigned* a, unsigned b0, unsigned b1) {
    asm volatile("mma.sync.aligned.m16n8k16.row.col.f32.bf16.bf16.f32 "
        "{%0,%1,%2,%3}, {%4,%5,%6,%7}, {%8,%9}, {%0,%1,%2,%3};"
        : "+f"(d[0]), "+f"(d[1]), "+f"(d[2]), "+f"(d[3])
        : "r"(a[0]), "r"(a[1]), "r"(a[2]), "r"(a[3]), "r"(b0), "r"(b1));
}
__device__ __forceinline__ void ldm4(unsigned* r, unsigned addr) {
    asm volatile("ldmatrix.sync.aligned.m8n8.x4.shared.b16 {%0,%1,%2,%3}, [%4];"
        : "=r"(r[0]), "=r"(r[1]), "=r"(r[2]), "=r"(r[3]) : "r"(addr));
}
__device__ __forceinline__ unsigned packbf(float lo, float hi) {
    unsigned r; asm("cvt.rn.bf16x2.f32 %0, %1, %2;" : "=r"(r) : "f"(hi), "f"(lo)); return r;
}

// ---------------- fp32 -> bf16 copy ----------------
__global__ __launch_bounds__(256) void conv_x(const float* __restrict__ x, bf16* __restrict__ o) {
    size_t i = ((size_t)blockIdx.x * 256 + threadIdx.x) * 4;
    float4 v = *(const float4*)(x + i);
    __nv_bfloat162* p = (__nv_bfloat162*)(o + i);
    p[0] = __floats2bfloat162_rn(v.x, v.y);
    p[1] = __floats2bfloat162_rn(v.z, v.w);
}

// ---------------- 4x W[k][n] fp32 -> Wt[n][k] bf16 (one launch) ----------------
__global__ __launch_bounds__(256) void conv_wt4(const float* __restrict__ W0,
                                                const float* __restrict__ W1,
                                                const float* __restrict__ W2,
                                                const float* __restrict__ W3,
                                                bf16* __restrict__ T0, bf16* __restrict__ T1,
                                                bf16* __restrict__ T2, bf16* __restrict__ T3) {
    __shared__ float tile[32][33];
    const int z = blockIdx.z;
    const float* W = (z == 0) ? W0 : (z == 1) ? W1 : (z == 2) ? W2 : W3;
    bf16* Wt = (z == 0) ? T0 : (z == 1) ? T1 : (z == 2) ? T2 : T3;
    const int bx = blockIdx.x << 5, by = blockIdx.y << 5;
    const int tx = threadIdx.x, ty = threadIdx.y;  // 32 x 8
    #pragma unroll
    for (int i = 0; i < 4; i++)
        tile[ty + 8*i][tx] = W[(size_t)(by + ty + 8*i) * DD + bx + tx];
    __syncthreads();
    #pragma unroll
    for (int i = 0; i < 4; i++)
        Wt[(size_t)(bx + ty + 8*i) * DD + by + tx] = __float2bfloat16(tile[tx][ty + 8*i]);
}

// ---------------- bf16 mma.sync GEMM body, 4-stage paired-barrier pipeline ----------------
// C = A[m][k] * Bt[n][k]^T + bias. Tile 128x128, k-chunk 32, 1 sync / 2 chunks.
#define GLD 40
#define GMB (128*GLD*2)      // bytes per matrix per stage (10240)
#define GSTB (2*GMB)         // per stage (A+B) 20480
__device__ __forceinline__ void gemm_body(const bf16* __restrict__ A,
                                          const bf16* __restrict__ Bt,
                                          const float* __restrict__ bias,
                                          const float* __restrict__ resid,
                                          void* __restrict__ outp, int mode,
                                          int m0, int n0, unsigned sbase) {
    const int tid = threadIdx.x;
    const int lane = tid & 31, w = tid >> 5;
    const int wm = (w >> 1) << 5;     // 4 warps in M
    const int wn = (w & 1) << 6;      // 2 warps in N
    const int g = lane >> 2, tig = lane & 3;
    const int lrow = lane & 15, lkh = (lane >> 4) << 3;

    const int crow = tid >> 1, cch = (tid & 1) << 4;
    const bf16* gA = A  + (size_t)(m0 + crow) * DD + cch;
    const bf16* gB = Bt + (size_t)(n0 + crow) * DD + cch;
    const unsigned sA = sbase + (crow * GLD + cch) * 2;
    const unsigned sB = sA + GMB;

    unsigned aoff[2], boff[4];
    #pragma unroll
    for (int mi = 0; mi < 2; mi++)
        aoff[mi] = sbase + ((wm + (mi<<4) + lrow) * GLD + lkh) * 2;
    #pragma unroll
    for (int jj = 0; jj < 4; jj++)
        boff[jj] = sbase + GMB + ((wn + (jj<<4) + lrow) * GLD + lkh) * 2;

    float acc[2][8][4];
    #pragma unroll
    for (int mi = 0; mi < 2; mi++)
        #pragma unroll
        for (int j = 0; j < 8; j++)
            #pragma unroll
            for (int r = 0; r < 4; r++) acc[mi][j][r] = 0.f;

    // prologue: k-chunks 0,1 into stages 0,1
    #pragma unroll
    for (int p = 0; p < 2; p++) {
        cp16(sA + p*GSTB,      gA + p*32);
        cp16(sA + p*GSTB + 16, gA + p*32 + 8);
        cp16(sB + p*GSTB,      gB + p*32);
        cp16(sB + p*GSTB + 16, gB + p*32 + 8);
    }
    cp_commit();

    for (int p = 0; p < 16; p++) {
        cp_wait<0>();
        __syncthreads();
        if (p < 15) {
            #pragma unroll
            for (int t = 0; t < 2; t++) {
                const int ch = 2*p + 2 + t;
                const unsigned ns = (unsigned)(ch & 3) * GSTB;
                cp16(sA + ns,      gA + ch*32);
                cp16(sA + ns + 16, gA + ch*32 + 8);
                cp16(sB + ns,      gB + ch*32);
                cp16(sB + ns + 16, gB + ch*32 + 8);
            }
            cp_commit();
        }
        #pragma unroll
        for (int h = 0; h < 2; h++) {
            const unsigned sb = (unsigned)((2*p + h) & 3) * GSTB;
            #pragma unroll
            for (int ks = 0; ks < 2; ks++) {
                unsigned a0[4], a1[4];
                ldm4(a0, aoff[0] + sb + ks*32);
                ldm4(a1, aoff[1] + sb + ks*32);
                #pragma unroll
                for (int jj = 0; jj < 4; jj++) {
                    unsigned b[4];
                    ldm4(b, boff[jj] + sb + ks*32);
                    mma16816(acc[0][2*jj],   a0, b[0], b[2]);
                    mma16816(acc[0][2*jj+1], a0, b[1], b[3]);
                    mma16816(acc[1][2*jj],   a1, b[0], b[2]);
                    mma16816(acc[1][2*jj+1], a1, b[1], b[3]);
                }
            }
        }
    }

    #pragma unroll
    for (int mi = 0; mi < 2; mi++) {
        #pragma unroll
        for (int j = 0; j < 8; j++) {
            const int r0 = m0 + wm + (mi<<4) + g;
            const int c0 = n0 + wn + (j<<3) + (tig<<1);
            const float bs0 = bias[c0], bs1 = bias[c0+1];
            float v00 = acc[mi][j][0] + bs0, v01 = acc[mi][j][1] + bs1;
            float v10 = acc[mi][j][2] + bs0, v11 = acc[mi][j][3] + bs1;
            if (mode == 1) {
                float* y = (float*)outp;
                float2 ra = *(const float2*)(resid + (size_t)r0 * DD + c0);
                float2 rb = *(const float2*)(resid + (size_t)(r0+8) * DD + c0);
                *(float2*)(y + (size_t)r0 * DD + c0)     = make_float2(v00 + ra.x, v01 + ra.y);
                *(float2*)(y + (size_t)(r0+8) * DD + c0) = make_float2(v10 + rb.x, v11 + rb.y);
            } else {
                bf16* o = (bf16*)outp;
                const int h_ = c0 >> 6, d_ = c0 & 63;
                const int b0_ = r0 >> 11, s0_ = r0 & 2047;
                const int b1_ = (r0+8) >> 11, s1_ = (r0+8) & 2047;
                if (mode == 0) {
                    *(__nv_bfloat162*)(o + ((((size_t)b0_*HH + h_)*SS + s0_) << 6) + d_) =
                        __floats2bfloat162_rn(v00, v01);
                    *(__nv_bfloat162*)(o + ((((size_t)b1_*HH + h_)*SS + s1_) << 6) + d_) =
                        __floats2bfloat162_rn(v10, v11);
                } else {  // mode 2: [b,h,d,s]
                    bf16* p0 = o + (((size_t)b0_*HH + h_)*DHH + d_) * SS + s0_;
                    bf16* p1 = o + (((size_t)b1_*HH + h_)*DHH + d_) * SS + s1_;
                    p0[0]  = __float2bfloat16(v00);
                    p0[SS] = __float2bfloat16(v01);
                    p1[0]  = __float2bfloat16(v10);
                    p1[SS] = __float2bfloat16(v11);
                }
            }
        }
    }
}

// fused Q/K/V projection: grid.x = 3 segments x 8 n-tiles
__global__ __launch_bounds__(256) void gemm_qkv(const bf16* __restrict__ A,
                                                const bf16* __restrict__ wq,
                                                const bf16* __restrict__ wk,
                                                const bf16* __restrict__ wv,
                                                const float* __restrict__ bq,
                                                const float* __restrict__ bk,
                                                const float* __restrict__ bv,
                                                bf16* __restrict__ qo,
                                                bf16* __restrict__ ko,
                                                bf16* __restrict__ vo) {
    extern __shared__ char dyn[];
    const unsigned sbase = (unsigned)__cvta_generic_to_shared(dyn);
    const int seg = blockIdx.x >> 3;
    const int n0 = (blockIdx.x & 7) << 7;
    const bf16*  Bt   = (seg == 0) ? wq : (seg == 1) ? wk : wv;
    const float* bias = (seg == 0) ? bq : (seg == 1) ? bk : bv;
    void* outp        = (seg == 0) ? (void*)qo : (seg == 1) ? (void*)ko : (void*)vo;
    const int mode    = (seg == 2) ? 2 : 0;
    gemm_body(A, Bt, bias, nullptr, outp, mode, blockIdx.y << 7, n0, sbase);
}

// output projection + residual (fp32 y)
__global__ __launch_bounds__(256) void gemm_o(const bf16* __restrict__ A,
                                              const bf16* __restrict__ Bt,
                                              const float* __restrict__ bias,
                                              const float* __restrict__ resid,
                                              float* __restrict__ y) {
    extern __shared__ char dyn[];
    const unsigned sbase = (unsigned)__cvta_generic_to_shared(dyn);
    gemm_body(A, Bt, bias, resid, (void*)y, 1, blockIdx.y << 7, blockIdx.x << 7, sbase);
}

// ---------------- flash attention: 4-stage paired barriers, mma row-sums ----------------
#define LDK 72
#define AMB (64*LDK*2)          // 9216 bytes per matrix per stage
#define ASTB (2*AMB)            // 18432 per stage (K+V)
#define AMS (4*ASTB)            // mask offset 73728
__global__ __launch_bounds__(256) void attn_mma(const float* __restrict__ mask,
                                                bf16* __restrict__ ctx) {
    extern __shared__ char dyn[];
    const unsigned sbase = (unsigned)__cvta_generic_to_shared(dyn);
    float* Ms = (float*)(dyn + AMS);
    const int bh = blockIdx.x, qt = blockIdx.y;
    const int b_ = bh >> 4, h_ = bh & 15;
    const int tid = threadIdx.x, lane = tid & 31, w = tid >> 5;
    const int g = lane >> 2, tig = lane & 3;
    const int lrow = lane & 15, lkh = (lane >> 4) << 3;
    const bf16* qg = g_q  + (size_t)bh * SS * DHH;
    const bf16* kg = g_k  + (size_t)bh * SS * DHH;
    const bf16* vg = g_vt + (size_t)bh * DHH * SS;

    const float LOG2E = 1.4426950408889634f;
    for (int i = tid; i < SS; i += 256) Ms[i] = mask[(size_t)b_ * SS + i] * LOG2E;

    // Q a-fragments from global (warp: rows qrow..qrow+15, all 64 dh)
    unsigned qa[4][4];
    const int qrow = (qt << 7) + (w << 4);
    #pragma unroll
    for (int kk = 0; kk < 4; kk++) {
        const bf16* qp = qg + (size_t)(qrow + g) * 64 + (kk<<4) + (tig<<1);
        qa[kk][0] = *(const unsigned*)qp;
        qa[kk][1] = *(const unsigned*)(qp + 8*64);
        qa[kk][2] = *(const unsigned*)(qp + 8);
        qa[kk][3] = *(const unsigned*)(qp + 8*64 + 8);
    }

    // cp.async mapping: row = tid>>2 (0..63), chunk = (tid&3)*16 elems (2 x cp16)
    const int crow = tid >> 2, cch = (tid & 3) << 4;
    const unsigned sK = sbase + (crow * LDK + cch) * 2;
    const unsigned sV = sK + AMB;
    const bf16* gK = kg + (size_t)crow * 64 + cch;           // + kt*64*64
    const bf16* gV = vg + (size_t)crow * SS + cch;           // + kt*64

    unsigned noff[4];
    #pragma unroll
    for (int jj = 0; jj < 4; jj++)
        noff[jj] = (((jj<<4) + lrow) * LDK + lkh) * 2;

    // all-ones B fragment for row-sum mma: only n-column 0 is 1.0 (lanes g==0)
    const unsigned onesb = (g == 0) ? 0x3F803F80u : 0u;

    float o[8][4];
    #pragma unroll
    for (int j = 0; j < 8; j++)
        #pragma unroll
        for (int r = 0; r < 4; r++) o[j][r] = 0.f;
    float csum[4] = {0.f, 0.f, 0.f, 0.f};   // row sums via mma (col 0 on tig==0 lanes)

    // prologue: key tiles 0,1 -> stages 0,1
    #pragma unroll
    for (int p = 0; p < 2; p++) {
        cp16(sK + p*ASTB,      gK + (size_t)p*64*64);
        cp16(sK + p*ASTB + 16, gK + (size_t)p*64*64 + 8);
        cp16(sV + p*ASTB,      gV + p*64);
        cp16(sV + p*ASTB + 16, gV + p*64 + 8);
    }
    cp_commit();

    const float SC = 0.125f * LOG2E;
    for (int p = 0; p < 16; p++) {
        cp_wait<0>();
        __syncthreads();
        if (p < 15) {
            #pragma unroll
            for (int t = 0; t < 2; t++) {
                const int nt = 2*p + 2 + t;
                const unsigned ns = (unsigned)(nt & 3) * ASTB;
                cp16(sK + ns,      gK + (size_t)nt*64*64);
                cp16(sK + ns + 16, gK + (size_t)nt*64*64 + 8);
                cp16(sV + ns,      gV + nt*64);
                cp16(sV + ns + 16, gV + nt*64 + 8);
            }
            cp_commit();
        }
        #pragma unroll
        for (int h = 0; h < 2; h++) {
            const int kt = 2*p + h;
            const unsigned kbase = sbase + (unsigned)(kt & 3) * ASTB;
            const unsigned vbase = kbase + AMB;
            const int kb = kt << 6;

            #pragma unroll
            for (int jj = 0; jj < 4; jj++) {
                // S block: 16 q-rows x 16 keys (keys 16*jj..16*jj+15)
                float c0[4] = {0.f,0.f,0.f,0.f}, c1[4] = {0.f,0.f,0.f,0.f};
                #pragma unroll
                for (int kk = 0; kk < 4; kk++) {
                    unsigned b[4];
                    ldm4(b, kbase + noff[jj] + kk*32);
                    mma16816(c0, qa[kk], b[0], b[2]);
                    mma16816(c1, qa[kk], b[1], b[3]);
                }
                const float2 mk0 = *(const float2*)(Ms + kb + (jj<<4) + (tig<<1));
                const float2 mk1 = *(const float2*)(Ms + kb + (jj<<4) + 8 + (tig<<1));
                c0[0] = exp2f(c0[0]*SC + mk0.x);
                c0[1] = exp2f(c0[1]*SC + mk0.y);
                c0[2] = exp2f(c0[2]*SC + mk0.x);
                c0[3] = exp2f(c0[3]*SC + mk0.y);
                c1[0] = exp2f(c1[0]*SC + mk1.x);
                c1[1] = exp2f(c1[1]*SC + mk1.y);
                c1[2] = exp2f(c1[2]*SC + mk1.x);
                c1[3] = exp2f(c1[3]*SC + mk1.y);
                unsigned pb[4];
                pb[0] = packbf(c0[0], c0[1]);
                pb[1] = packbf(c0[2], c0[3]);
                pb[2] = packbf(c1[0], c1[1]);
                pb[3] = packbf(c1[2], c1[3]);
                // row sums: P block @ ones column
                mma16816(csum, pb, onesb, onesb);
                // O += P block @ V block
                #pragma unroll
                for (int jv = 0; jv < 4; jv++) {
                    unsigned bv[4];
                    ldm4(bv, vbase + noff[jv] + jj*32);
                    mma16816(o[2*jv],   pb, bv[0], bv[2]);
                    mma16816(o[2*jv+1], pb, bv[1], bv[3]);
                }
            }
        }
    }

    // row sums live in csum[0]/csum[2] of tig==0 lanes; broadcast within quad
    const int qlane = lane & 28;
    const float s0 = __shfl_sync(0xffffffffu, csum[0], qlane);
    const float s1 = __shfl_sync(0xffffffffu, csum[2], qlane);
    const float inv0 = 1.0f / s0, inv1 = 1.0f / s1;
    const int r0 = qrow + g;
    #pragma unroll
    for (int j = 0; j < 8; j++) {
        const int col = (h_ << 6) + (j<<3) + (tig<<1);
        *(__nv_bfloat162*)(ctx + ((size_t)b_*SS + r0) * DD + col) =
            __floats2bfloat162_rn(o[j][0]*inv0, o[j][1]*inv0);
        *(__nv_bfloat162*)(ctx + ((size_t)b_*SS + r0 + 8) * DD + col) =
            __floats2bfloat162_rn(o[j][2]*inv1, o[j][3]*inv1);
    }
}

// ---------------- LayerNorm (fp32) ----------------
__global__ __launch_bounds__(256) void ln_kernel(const float* __restrict__ y,
                                                 const float* __restrict__ gamma,
                                                 const float* __restrict__ beta,
                                                 float* __restrict__ out) {
    const int row = blockIdx.x;
    const int tid = threadIdx.x;
    const float* yr = y + (size_t)row * DD;
    const int c = tid << 2;
    float4 v = *(const float4*)(yr + c);
    float s  = v.x + v.y + v.z + v.w;
    float ss = v.x*v.x + v.y*v.y + v.z*v.z + v.w*v.w;
    #pragma unroll
    for (int off = 16; off > 0; off >>= 1) {
        s  += __shfl_xor_sync(0xffffffffu, s,  off);
        ss += __shfl_xor_sync(0xffffffffu, ss, off);
    }
    __shared__ float rs[8], rss[8];
    if ((tid & 31) == 0) { rs[tid >> 5] = s; rss[tid >> 5] = ss; }
    __syncthreads();
    if (tid < 32) {
        float a = (tid < 8) ? rs[tid] : 0.f;
        float b = (tid < 8) ? rss[tid] : 0.f;
        #pragma unroll
        for (int off = 4; off > 0; off >>= 1) {
            a += __shfl_xor_sync(0xffffffffu, a, off);
            b += __shfl_xor_sync(0xffffffffu, b, off);
        }
        if (tid == 0) { rs[0] = a; rss[0] = b; }
    }
    __syncthreads();
    const float mu  = rs[0] * (1.0f / 1024.0f);
    const float var = rss[0] * (1.0f / 1024.0f) - mu * mu;
    const float r = rsqrtf(var + 1e-12f);
    float4 gv = *(const float4*)(gamma + c);
    float4 bt = *(const float4*)(beta + c);
    float4 ov;
    ov.x = (v.x - mu) * r * gv.x + bt.x;
    ov.y = (v.y - mu) * r * gv.y + bt.y;
    ov.z = (v.z - mu) * r * gv.z + bt.z;
    ov.w = (v.w - mu) * r * gv.w + bt.w;
    *(float4*)(out + (size_t)row * DD + c) = ov;
}

extern "C" void kernel_launch(void* const* d_in, const int* in_sizes, int n_in,
                              void* d_out, int out_size) {
    (void)in_sizes; (void)n_in; (void)out_size;
    const float* x     = (const float*)d_in[0];
    const float* mask  = (const float*)d_in[1];
    const float* Wq    = (const float*)d_in[2];
    const float* bq    = (const float*)d_in[3];
    const float* Wk    = (const float*)d_in[4];
    const float* bk    = (const float*)d_in[5];
    const float* Wv    = (const float*)d_in[6];
    const float* bv    = (const float*)d_in[7];
    const float* Wo    = (const float*)d_in[8];
    const float* bo    = (const float*)d_in[9];
    const float* gamma = (const float*)d_in[10];
    const float* beta  = (const float*)d_in[11];
    float* out = (float*)d_out;

    bf16 *xb, *wq, *wk, *wv, *wo, *qp, *kp, *vtp, *ctxp;
    float *yp;
    cudaGetSymbolAddress((void**)&xb,   g_xb);
    cudaGetSymbolAddress((void**)&wq,   g_wq);
    cudaGetSymbolAddress((void**)&wk,   g_wk);
    cudaGetSymbolAddress((void**)&wv,   g_wv);
    cudaGetSymbolAddress((void**)&wo,   g_wo);
    cudaGetSymbolAddress((void**)&qp,   g_q);
    cudaGetSymbolAddress((void**)&kp,   g_k);
    cudaGetSymbolAddress((void**)&vtp,  g_vt);
    cudaGetSymbolAddress((void**)&ctxp, g_ctx);
    cudaGetSymbolAddress((void**)&yp,   g_y);

    const int gemm_smem = 4 * GSTB;               // 81920
    const int attn_smem = AMS + SS * 4;           // 81920
    cudaFuncSetAttribute(gemm_qkv, cudaFuncAttributeMaxDynamicSharedMemorySize, gemm_smem);
    cudaFuncSetAttribute(gemm_o,   cudaFuncAttributeMaxDynamicSharedMemorySize, gemm_smem);
    cudaFuncSetAttribute(attn_mma, cudaFuncAttributeMaxDynamicSharedMemorySize, attn_smem);

    conv_x<<<(int)(((size_t)MM*DD)/1024), 256>>>(x, xb);
    conv_wt4<<<dim3(32, 32, 4), dim3(32, 8)>>>(Wq, Wk, Wv, Wo, wq, wk, wv, wo);

    gemm_qkv<<<dim3(24, MM/128), 256, gemm_smem>>>(xb, wq, wk, wv, bq, bk, bv, qp, kp, vtp);

    attn_mma<<<dim3(64, 16), 256, attn_smem>>>(mask, ctxp);

    gemm_o<<<dim3(DD/128, MM/128), 256, gemm_smem>>>(ctxp, wo, bo, x, yp);
    ln_kernel<<<MM, 256>>>(yp, gamma, beta, out);
}

// round 11
// speedup vs baseline: 1.7583x; 1.7583x over previous
#include <cuda_runtime.h>
#include <cuda_bf16.h>
#include <cuda_fp16.h>
#include <cstdint>
#include <math.h>

#define BB 4
#define SS 2048
#define DD 1024
#define HH 16
#define DHH 64
#define MM (BB*SS)

typedef __nv_bfloat16 bf16;

// ---------------- device scratch (allocation-free rule) ----------------
__device__ bf16   g_xb[(size_t)MM*DD];      // x in bf16 [m][k]
__device__ bf16   g_wq[DD*DD];              // W^T bf16 [n][k]
__device__ bf16   g_wk[DD*DD];
__device__ bf16   g_wv[DD*DD];
__device__ bf16   g_wo[DD*DD];
__device__ bf16   g_q [(size_t)MM*DD];      // [b,h,s,d]
__device__ bf16   g_k [(size_t)MM*DD];      // [b,h,s,d]
__device__ __half g_vt[(size_t)MM*DD];      // [b,h,d,s] fp16 (transposed for PV)
__device__ bf16   g_ctx[(size_t)MM*DD];     // [m][n]
__device__ float  g_y [(size_t)MM*DD];      // pre-LN fp32

// ---------------- helpers ----------------
__device__ __forceinline__ void cp16(unsigned dst, const void* src) {
    asm volatile("cp.async.cg.shared.global [%0], [%1], 16;\n" :: "r"(dst), "l"(src));
}
__device__ __forceinline__ void cp_commit() { asm volatile("cp.async.commit_group;\n"); }
template<int N> __device__ __forceinline__ void cp_wait() {
    asm volatile("cp.async.wait_group %0;\n" :: "n"(N));
}
__device__ __forceinline__ void mma16816(float* d, const unsigned* a, unsigned b0, unsigned b1) {
    asm volatile("mma.sync.aligned.m16n8k16.row.col.f32.bf16.bf16.f32 "
        "{%0,%1,%2,%3}, {%4,%5,%6,%7}, {%8,%9}, {%0,%1,%2,%3};"
        : "+f"(d[0]), "+f"(d[1]), "+f"(d[2]), "+f"(d[3])
        : "r"(a[0]), "r"(a[1]), "r"(a[2]), "r"(a[3]), "r"(b0), "r"(b1));
}
__device__ __forceinline__ void mma16816h(float* d, const unsigned* a, unsigned b0, unsigned b1) {
    asm volatile("mma.sync.aligned.m16n8k16.row.col.f32.f16.f16.f32 "
        "{%0,%1,%2,%3}, {%4,%5,%6,%7}, {%8,%9}, {%0,%1,%2,%3};"
        : "+f"(d[0]), "+f"(d[1]), "+f"(d[2]), "+f"(d[3])
        : "r"(a[0]), "r"(a[1]), "r"(a[2]), "r"(a[3]), "r"(b0), "r"(b1));
}
__device__ __forceinline__ void ldm4(unsigned* r, unsigned addr) {
    asm volatile("ldmatrix.sync.aligned.m8n8.x4.shared.b16 {%0,%1,%2,%3}, [%4];"
        : "=r"(r[0]), "=r"(r[1]), "=r"(r[2]), "=r"(r[3]) : "r"(addr));
}
// pack 2 fp32 -> f16x2, then 2^x elementwise (one MUFU op per pair)
__device__ __forceinline__ unsigned exp2x2(float lo, float hi) {
    unsigned h, r;
    asm("cvt.rn.f16x2.f32 %0, %1, %2;" : "=r"(h) : "f"(hi), "f"(lo));
    asm("ex2.approx.f16x2 %0, %1;" : "=r"(r) : "r"(h));
    return r;
}

// ---------------- fp32 -> bf16 copy ----------------
__global__ __launch_bounds__(256) void conv_x(const float* __restrict__ x, bf16* __restrict__ o) {
    size_t i = ((size_t)blockIdx.x * 256 + threadIdx.x) * 4;
    float4 v = *(const float4*)(x + i);
    __nv_bfloat162* p = (__nv_bfloat162*)(o + i);
    p[0] = __floats2bfloat162_rn(v.x, v.y);
    p[1] = __floats2bfloat162_rn(v.z, v.w);
}

// ---------------- 4x W[k][n] fp32 -> Wt[n][k] bf16 (one launch) ----------------
__global__ __launch_bounds__(256) void conv_wt4(const float* __restrict__ W0,
                                                const float* __restrict__ W1,
                                                const float* __restrict__ W2,
                                                const float* __restrict__ W3,
                                                bf16* __restrict__ T0, bf16* __restrict__ T1,
                                                bf16* __restrict__ T2, bf16* __restrict__ T3) {
    __shared__ float tile[32][33];
    const int z = blockIdx.z;
    const float* W = (z == 0) ? W0 : (z == 1) ? W1 : (z == 2) ? W2 : W3;
    bf16* Wt = (z == 0) ? T0 : (z == 1) ? T1 : (z == 2) ? T2 : T3;
    const int bx = blockIdx.x << 5, by = blockIdx.y << 5;
    const int tx = threadIdx.x, ty = threadIdx.y;  // 32 x 8
    #pragma unroll
    for (int i = 0; i < 4; i++)
        tile[ty + 8*i][tx] = W[(size_t)(by + ty + 8*i) * DD + bx + tx];
    __syncthreads();
    #pragma unroll
    for (int i = 0; i < 4; i++)
        Wt[(size_t)(bx + ty + 8*i) * DD + by + tx] = __float2bfloat16(tile[tx][ty + 8*i]);
}

// ---------------- bf16 mma.sync GEMM body, 3-stage cp.async + ldmatrix ----------------
// C = A[m][k] * Bt[n][k]^T + bias. Tile 128x128, k-chunk 32.
// mode 0: bf16 -> [b,h,s,d]; mode 2: fp16 -> [b,h,d,s]; mode 1: fp32 C+resid.
#define GLD 40
#define GMB (128*GLD*2)      // bytes per matrix per stage (10240)
#define GSTB (2*GMB)         // per stage (A+B) 20480
__device__ __forceinline__ void gemm_body(const bf16* __restrict__ A,
                                          const bf16* __restrict__ Bt,
                                          const float* __restrict__ bias,
                                          const float* __restrict__ resid,
                                          void* __restrict__ outp, int mode,
                                          int m0, int n0, unsigned sbase) {
    const int tid = threadIdx.x;
    const int lane = tid & 31, w = tid >> 5;
    const int wm = (w >> 1) << 5;     // 4 warps in M
    const int wn = (w & 1) << 6;      // 2 warps in N
    const int g = lane >> 2, tig = lane & 3;
    const int lrow = lane & 15, lkh = (lane >> 4) << 3;

    const int crow = tid >> 1, cch = (tid & 1) << 4;
    const bf16* gA = A  + (size_t)(m0 + crow) * DD + cch;
    const bf16* gB = Bt + (size_t)(n0 + crow) * DD + cch;
    const unsigned sA = sbase + (crow * GLD + cch) * 2;
    const unsigned sB = sA + GMB;

    unsigned aoff[2], boff[4];
    #pragma unroll
    for (int mi = 0; mi < 2; mi++)
        aoff[mi] = sbase + ((wm + (mi<<4) + lrow) * GLD + lkh) * 2;
    #pragma unroll
    for (int jj = 0; jj < 4; jj++)
        boff[jj] = sbase + GMB + ((wn + (jj<<4) + lrow) * GLD + lkh) * 2;

    float acc[2][8][4];
    #pragma unroll
    for (int mi = 0; mi < 2; mi++)
        #pragma unroll
        for (int j = 0; j < 8; j++)
            #pragma unroll
            for (int r = 0; r < 4; r++) acc[mi][j][r] = 0.f;

    #pragma unroll
    for (int p = 0; p < 2; p++) {
        cp16(sA + p*GSTB,      gA + p*32);
        cp16(sA + p*GSTB + 16, gA + p*32 + 8);
        cp16(sB + p*GSTB,      gB + p*32);
        cp16(sB + p*GSTB + 16, gB + p*32 + 8);
        cp_commit();
    }

    for (int it = 0; it < 32; it++) {
        if (it == 31) cp_wait<0>(); else cp_wait<1>();
        __syncthreads();
        const int nit = it + 2;
        if (nit < 32) {
            const unsigned ns = (unsigned)(nit % 3) * GSTB;
            cp16(sA + ns,      gA + nit*32);
            cp16(sA + ns + 16, gA + nit*32 + 8);
            cp16(sB + ns,      gB + nit*32);
            cp16(sB + ns + 16, gB + nit*32 + 8);
            cp_commit();
        }
        const unsigned sb = (unsigned)(it % 3) * GSTB;
        #pragma unroll
        for (int ks = 0; ks < 2; ks++) {
            unsigned a0[4], a1[4];
            ldm4(a0, aoff[0] + sb + ks*32);
            ldm4(a1, aoff[1] + sb + ks*32);
            #pragma unroll
            for (int jj = 0; jj < 4; jj++) {
                unsigned b[4];
                ldm4(b, boff[jj] + sb + ks*32);
                mma16816(acc[0][2*jj],   a0, b[0], b[2]);
                mma16816(acc[0][2*jj+1], a0, b[1], b[3]);
                mma16816(acc[1][2*jj],   a1, b[0], b[2]);
                mma16816(acc[1][2*jj+1], a1, b[1], b[3]);
            }
        }
    }

    #pragma unroll
    for (int mi = 0; mi < 2; mi++) {
        #pragma unroll
        for (int j = 0; j < 8; j++) {
            const int r0 = m0 + wm + (mi<<4) + g;
            const int c0 = n0 + wn + (j<<3) + (tig<<1);
            const float bs0 = bias[c0], bs1 = bias[c0+1];
            float v00 = acc[mi][j][0] + bs0, v01 = acc[mi][j][1] + bs1;
            float v10 = acc[mi][j][2] + bs0, v11 = acc[mi][j][3] + bs1;
            if (mode == 1) {
                float* y = (float*)outp;
                float2 ra = *(const float2*)(resid + (size_t)r0 * DD + c0);
                float2 rb = *(const float2*)(resid + (size_t)(r0+8) * DD + c0);
                *(float2*)(y + (size_t)r0 * DD + c0)     = make_float2(v00 + ra.x, v01 + ra.y);
                *(float2*)(y + (size_t)(r0+8) * DD + c0) = make_float2(v10 + rb.x, v11 + rb.y);
            } else {
                const int h_ = c0 >> 6, d_ = c0 & 63;
                const int b0_ = r0 >> 11, s0_ = r0 & 2047;
                const int b1_ = (r0+8) >> 11, s1_ = (r0+8) & 2047;
                if (mode == 0) {
                    bf16* o = (bf16*)outp;
                    *(__nv_bfloat162*)(o + ((((size_t)b0_*HH + h_)*SS + s0_) << 6) + d_) =
                        __floats2bfloat162_rn(v00, v01);
                    *(__nv_bfloat162*)(o + ((((size_t)b1_*HH + h_)*SS + s1_) << 6) + d_) =
                        __floats2bfloat162_rn(v10, v11);
                } else {  // mode 2: fp16 [b,h,d,s]
                    __half* o = (__half*)outp;
                    __half* p0 = o + (((size_t)b0_*HH + h_)*DHH + d_) * SS + s0_;
                    __half* p1 = o + (((size_t)b1_*HH + h_)*DHH + d_) * SS + s1_;
                    p0[0]  = __float2half(v00);
                    p0[SS] = __float2half(v01);
                    p1[0]  = __float2half(v10);
                    p1[SS] = __float2half(v11);
                }
            }
        }
    }
}

// fused Q/K/V projection: grid.x = 3 segments x 8 n-tiles
__global__ __launch_bounds__(256) void gemm_qkv(const bf16* __restrict__ A,
                                                const bf16* __restrict__ wq,
                                                const bf16* __restrict__ wk,
                                                const bf16* __restrict__ wv,
                                                const float* __restrict__ bq,
                                                const float* __restrict__ bk,
                                                const float* __restrict__ bv,
                                                bf16* __restrict__ qo,
                                                bf16* __restrict__ ko,
                                                __half* __restrict__ vo) {
    extern __shared__ char dyn[];
    const unsigned sbase = (unsigned)__cvta_generic_to_shared(dyn);
    const int seg = blockIdx.x >> 3;
    const int n0 = (blockIdx.x & 7) << 7;
    const bf16*  Bt   = (seg == 0) ? wq : (seg == 1) ? wk : wv;
    const float* bias = (seg == 0) ? bq : (seg == 1) ? bk : bv;
    void* outp        = (seg == 0) ? (void*)qo : (seg == 1) ? (void*)ko : (void*)vo;
    const int mode    = (seg == 2) ? 2 : 0;
    gemm_body(A, Bt, bias, nullptr, outp, mode, blockIdx.y << 7, n0, sbase);
}

// output projection + residual (fp32 y)
__global__ __launch_bounds__(256) void gemm_o(const bf16* __restrict__ A,
                                              const bf16* __restrict__ Bt,
                                              const float* __restrict__ bias,
                                              const float* __restrict__ resid,
                                              float* __restrict__ y) {
    extern __shared__ char dyn[];
    const unsigned sbase = (unsigned)__cvta_generic_to_shared(dyn);
    gemm_body(A, Bt, bias, resid, (void*)y, 1, blockIdx.y << 7, blockIdx.x << 7, sbase);
}

// ---------------- flash attention: fp16 ex2x2 softmax, mma row-sums ----------------
#define LDK 72
#define AMB (64*LDK*2)          // 9216 bytes per matrix per stage
#define ASTB (2*AMB)            // 18432 per stage (K+V)
#define AMS (3*ASTB)            // mask offset 55296
__global__ __launch_bounds__(256) void attn_mma(const float* __restrict__ mask,
                                                bf16* __restrict__ ctx) {
    extern __shared__ char dyn[];
    const unsigned sbase = (unsigned)__cvta_generic_to_shared(dyn);
    float* Ms = (float*)(dyn + AMS);
    const int bh = blockIdx.x, qt = blockIdx.y;
    const int b_ = bh >> 4, h_ = bh & 15;
    const int tid = threadIdx.x, lane = tid & 31, w = tid >> 5;
    const int g = lane >> 2, tig = lane & 3;
    const int lrow = lane & 15, lkh = (lane >> 4) << 3;
    const bf16*   qg = g_q  + (size_t)bh * SS * DHH;
    const bf16*   kg = g_k  + (size_t)bh * SS * DHH;
    const __half* vg = g_vt + (size_t)bh * DHH * SS;

    const float LOG2E = 1.4426950408889634f;
    for (int i = tid; i < SS; i += 256) Ms[i] = mask[(size_t)b_ * SS + i] * LOG2E;

    // Q a-fragments from global (warp: rows qrow..qrow+15, all 64 dh)
    unsigned qa[4][4];
    const int qrow = (qt << 7) + (w << 4);
    #pragma unroll
    for (int kk = 0; kk < 4; kk++) {
        const bf16* qp = qg + (size_t)(qrow + g) * 64 + (kk<<4) + (tig<<1);
        qa[kk][0] = *(const unsigned*)qp;
        qa[kk][1] = *(const unsigned*)(qp + 8*64);
        qa[kk][2] = *(const unsigned*)(qp + 8);
        qa[kk][3] = *(const unsigned*)(qp + 8*64 + 8);
    }

    // cp.async mapping: row = tid>>2 (0..63), chunk = (tid&3)*16 elems (2 x cp16)
    const int crow = tid >> 2, cch = (tid & 3) << 4;
    const unsigned sK = sbase + (crow * LDK + cch) * 2;
    const unsigned sV = sK + AMB;
    const bf16*   gK = kg + (size_t)crow * 64 + cch;         // + kt*64*64
    const __half* gV = vg + (size_t)crow * SS + cch;         // + kt*64

    unsigned noff[4];
    #pragma unroll
    for (int jj = 0; jj < 4; jj++)
        noff[jj] = (((jj<<4) + lrow) * LDK + lkh) * 2;

    // fp16 ones B-fragment: only n-column 0 is 1.0 (lanes g==0)
    const unsigned onesh = (g == 0) ? 0x3C003C00u : 0u;

    float o[8][4];
    #pragma unroll
    for (int j = 0; j < 8; j++)
        #pragma unroll
        for (int r = 0; r < 4; r++) o[j][r] = 0.f;
    float csA[4] = {0.f,0.f,0.f,0.f};   // row-sum accumulators (alternating, for ILP)
    float csB[4] = {0.f,0.f,0.f,0.f};

    // prologue: key tiles 0,1
    #pragma unroll
    for (int p = 0; p < 2; p++) {
        cp16(sK + p*ASTB,      gK + (size_t)p*64*64);
        cp16(sK + p*ASTB + 16, gK + (size_t)p*64*64 + 8);
        cp16(sV + p*ASTB,      gV + p*64);
        cp16(sV + p*ASTB + 16, gV + p*64 + 8);
        cp_commit();
    }

    const float SC = 0.125f * LOG2E;
    for (int kt = 0; kt < 32; kt++) {
        if (kt == 31) cp_wait<0>(); else cp_wait<1>();
        __syncthreads();
        const int nkt = kt + 2;
        if (nkt < 32) {
            const unsigned ns = (unsigned)(nkt % 3) * ASTB;
            cp16(sK + ns,      gK + (size_t)nkt*64*64);
            cp16(sK + ns + 16, gK + (size_t)nkt*64*64 + 8);
            cp16(sV + ns,      gV + nkt*64);
            cp16(sV + ns + 16, gV + nkt*64 + 8);
            cp_commit();
        }
        const unsigned sb = (unsigned)(kt % 3) * ASTB;
        const unsigned kbase = sbase + sb;
        const unsigned vbase = kbase + AMB;

        // S = Q @ K^T  (warp: 16 x 64), 8 independent accumulator chains
        float c[8][4];
        #pragma unroll
        for (int j = 0; j < 8; j++)
            #pragma unroll
            for (int r = 0; r < 4; r++) c[j][r] = 0.f;
        #pragma unroll
        for (int kk = 0; kk < 4; kk++) {
            #pragma unroll
            for (int jj = 0; jj < 4; jj++) {
                unsigned b[4];
                ldm4(b, kbase + noff[jj] + kk*32);
                mma16816(c[2*jj],   qa[kk], b[0], b[2]);
                mma16816(c[2*jj+1], qa[kk], b[1], b[3]);
            }
        }

        // t = s*SC + mask2 (fp32), then packed fp16 exp2 -> P a-fragments
        const int kb = kt << 6;
        #pragma unroll
        for (int j = 0; j < 8; j++) {
            float2 mk = *(const float2*)(Ms + kb + (j<<3) + (tig<<1));
            c[j][0] = c[j][0]*SC + mk.x;
            c[j][1] = c[j][1]*SC + mk.y;
            c[j][2] = c[j][2]*SC + mk.x;
            c[j][3] = c[j][3]*SC + mk.y;
        }
        unsigned pb[4][4];
        #pragma unroll
        for (int kk = 0; kk < 4; kk++) {
            pb[kk][0] = exp2x2(c[2*kk][0],   c[2*kk][1]);
            pb[kk][1] = exp2x2(c[2*kk][2],   c[2*kk][3]);
            pb[kk][2] = exp2x2(c[2*kk+1][0], c[2*kk+1][1]);
            pb[kk][3] = exp2x2(c[2*kk+1][2], c[2*kk+1][3]);
        }

        // row sums via ones-column fp16 MMA (2 independent accumulators)
        mma16816h(csA, pb[0], onesh, onesh);
        mma16816h(csB, pb[1], onesh, onesh);
        mma16816h(csA, pb[2], onesh, onesh);
        mma16816h(csB, pb[3], onesh, onesh);

        // O += P @ V  (fp16 x fp16 -> fp32; Vs rows = dh, cols = key)
        #pragma unroll
        for (int kk = 0; kk < 4; kk++) {
            #pragma unroll
            for (int jj = 0; jj < 4; jj++) {
                unsigned b[4];
                ldm4(b, vbase + noff[jj] + kk*32);
                mma16816h(o[2*jj],   pb[kk], b[0], b[2]);
                mma16816h(o[2*jj+1], pb[kk], b[1], b[3]);
            }
        }
    }

    // row sums sit in col 0 (tig==0 lanes): regs 0 (row g) and 2 (row g+8)
    const int qlane = lane & 28;
    const float s0 = __shfl_sync(0xffffffffu, csA[0] + csB[0], qlane);
    const float s1 = __shfl_sync(0xffffffffu, csA[2] + csB[2], qlane);
    const float inv0 = 1.0f / s0, inv1 = 1.0f / s1;
    const int r0 = qrow + g;
    #pragma unroll
    for (int j = 0; j < 8; j++) {
        const int col = (h_ << 6) + (j<<3) + (tig<<1);
        *(__nv_bfloat162*)(ctx + ((size_t)b_*SS + r0) * DD + col) =
            __floats2bfloat162_rn(o[j][0]*inv0, o[j][1]*inv0);
        *(__nv_bfloat162*)(ctx + ((size_t)b_*SS + r0 + 8) * DD + col) =
            __floats2bfloat162_rn(o[j][2]*inv1, o[j][3]*inv1);
    }
}

// ---------------- LayerNorm (fp32) ----------------
__global__ __launch_bounds__(256) void ln_kernel(const float* __restrict__ y,
                                                 const float* __restrict__ gamma,
                                                 const float* __restrict__ beta,
                                                 float* __restrict__ out) {
    const int row = blockIdx.x;
    const int tid = threadIdx.x;
    const float* yr = y + (size_t)row * DD;
    const int c = tid << 2;
    float4 v = *(const float4*)(yr + c);
    float s  = v.x + v.y + v.z + v.w;
    float ss = v.x*v.x + v.y*v.y + v.z*v.z + v.w*v.w;
    #pragma unroll
    for (int off = 16; off > 0; off >>= 1) {
        s  += __shfl_xor_sync(0xffffffffu, s,  off);
        ss += __shfl_xor_sync(0xffffffffu, ss, off);
    }
    __shared__ float rs[8], rss[8];
    if ((tid & 31) == 0) { rs[tid >> 5] = s; rss[tid >> 5] = ss; }
    __syncthreads();
    if (tid < 32) {
        float a = (tid < 8) ? rs[tid] : 0.f;
        float b = (tid < 8) ? rss[tid] : 0.f;
        #pragma unroll
        for (int off = 4; off > 0; off >>= 1) {
            a += __shfl_xor_sync(0xffffffffu, a, off);
            b += __shfl_xor_sync(0xffffffffu, b, off);
        }
        if (tid == 0) { rs[0] = a; rss[0] = b; }
    }
    __syncthreads();
    const float mu  = rs[0] * (1.0f / 1024.0f);
    const float var = rss[0] * (1.0f / 1024.0f) - mu * mu;
    const float r = rsqrtf(var + 1e-12f);
    float4 gv = *(const float4*)(gamma + c);
    float4 bt = *(const float4*)(beta + c);
    float4 ov;
    ov.x = (v.x - mu) * r * gv.x + bt.x;
    ov.y = (v.y - mu) * r * gv.y + bt.y;
    ov.z = (v.z - mu) * r * gv.z + bt.z;
    ov.w = (v.w - mu) * r * gv.w + bt.w;
    *(float4*)(out + (size_t)row * DD + c) = ov;
}

extern "C" void kernel_launch(void* const* d_in, const int* in_sizes, int n_in,
                              void* d_out, int out_size) {
    (void)in_sizes; (void)n_in; (void)out_size;
    const float* x     = (const float*)d_in[0];
    const float* mask  = (const float*)d_in[1];
    const float* Wq    = (const float*)d_in[2];
    const float* bq    = (const float*)d_in[3];
    const float* Wk    = (const float*)d_in[4];
    const float* bk    = (const float*)d_in[5];
    const float* Wv    = (const float*)d_in[6];
    const float* bv    = (const float*)d_in[7];
    const float* Wo    = (const float*)d_in[8];
    const float* bo    = (const float*)d_in[9];
    const float* gamma = (const float*)d_in[10];
    const float* beta  = (const float*)d_in[11];
    float* out = (float*)d_out;

    bf16 *xb, *wq, *wk, *wv, *wo, *qp, *kp, *ctxp;
    __half *vtp;
    float *yp;
    cudaGetSymbolAddress((void**)&xb,   g_xb);
    cudaGetSymbolAddress((void**)&wq,   g_wq);
    cudaGetSymbolAddress((void**)&wk,   g_wk);
    cudaGetSymbolAddress((void**)&wv,   g_wv);
    cudaGetSymbolAddress((void**)&wo,   g_wo);
    cudaGetSymbolAddress((void**)&qp,   g_q);
    cudaGetSymbolAddress((void**)&kp,   g_k);
    cudaGetSymbolAddress((void**)&vtp,  g_vt);
    cudaGetSymbolAddress((void**)&ctxp, g_ctx);
    cudaGetSymbolAddress((void**)&yp,   g_y);

    const int gemm_smem = 3 * GSTB;               // 61440
    const int attn_smem = AMS + SS * 4;           // 63488
    cudaFuncSetAttribute(gemm_qkv, cudaFuncAttributeMaxDynamicSharedMemorySize, gemm_smem);
    cudaFuncSetAttribute(gemm_o,   cudaFuncAttributeMaxDynamicSharedMemorySize, gemm_smem);
    cudaFuncSetAttribute(attn_mma, cudaFuncAttributeMaxDynamicSharedMemorySize, attn_smem);

    conv_x<<<(int)(((size_t)MM*DD)/1024), 256>>>(x, xb);
    conv_wt4<<<dim3(32, 32, 4), dim3(32, 8)>>>(Wq, Wk, Wv, Wo, wq, wk, wv, wo);

    gemm_qkv<<<dim3(24, MM/128), 256, gemm_smem>>>(xb, wq, wk, wv, bq, bk, bv, qp, kp, vtp);

    attn_mma<<<dim3(64, 16), 256, attn_smem>>>(mask, ctxp);

    gemm_o<<<dim3(DD/128, MM/128), 256, gemm_smem>>>(ctxp, wo, bo, x, yp);
    ln_kernel<<<MM, 256>>>(yp, gamma, beta, out);
}

// round 12
// speedup vs baseline: 1.8680x; 1.0624x over previous
#include <cuda_runtime.h>
#include <cuda_bf16.h>
#include <cuda_fp16.h>
#include <cstdint>
#include <math.h>

#define BB 4
#define SS 2048
#define DD 1024
#define HH 16
#define DHH 64
#define MM (BB*SS)

typedef __half fp16;

// ---------------- device scratch (allocation-free rule) ----------------
__device__ fp16  g_xb[(size_t)MM*DD];      // x in fp16 [m][k]
__device__ fp16  g_wq[DD*DD];              // W^T fp16 [n][k]
__device__ fp16  g_wk[DD*DD];
__device__ fp16  g_wv[DD*DD];
__device__ fp16  g_wo[DD*DD];
__device__ fp16  g_q [(size_t)MM*DD];      // [b,h,s,d]
__device__ fp16  g_k [(size_t)MM*DD];      // [b,h,s,d]
__device__ fp16  g_vt[(size_t)MM*DD];      // [b,h,d,s]  (transposed for PV)
__device__ fp16  g_ctx[(size_t)MM*DD];     // [m][n]
__device__ float g_y [(size_t)MM*DD];      // pre-LN fp32

// ---------------- helpers ----------------
__device__ __forceinline__ void cp16(unsigned dst, const void* src) {
    asm volatile("cp.async.cg.shared.global [%0], [%1], 16;\n" :: "r"(dst), "l"(src));
}
__device__ __forceinline__ void cp_commit() { asm volatile("cp.async.commit_group;\n"); }
template<int N> __device__ __forceinline__ void cp_wait() {
    asm volatile("cp.async.wait_group %0;\n" :: "n"(N));
}
// fp16 x fp16 -> fp16 accumulate (2x rate vs f32 acc on legacy HMMA path)
__device__ __forceinline__ void mma16816hh(unsigned* d, const unsigned* a, unsigned b0, unsigned b1) {
    asm volatile("mma.sync.aligned.m16n8k16.row.col.f16.f16.f16.f16 "
        "{%0,%1}, {%2,%3,%4,%5}, {%6,%7}, {%0,%1};"
        : "+r"(d[0]), "+r"(d[1])
        : "r"(a[0]), "r"(a[1]), "r"(a[2]), "r"(a[3]), "r"(b0), "r"(b1));
}
// fp16 x fp16 -> fp32 accumulate (row sums only)
__device__ __forceinline__ void mma16816h(float* d, const unsigned* a, unsigned b0, unsigned b1) {
    asm volatile("mma.sync.aligned.m16n8k16.row.col.f32.f16.f16.f32 "
        "{%0,%1,%2,%3}, {%4,%5,%6,%7}, {%8,%9}, {%0,%1,%2,%3};"
        : "+f"(d[0]), "+f"(d[1]), "+f"(d[2]), "+f"(d[3])
        : "r"(a[0]), "r"(a[1]), "r"(a[2]), "r"(a[3]), "r"(b0), "r"(b1));
}
__device__ __forceinline__ void ldm4(unsigned* r, unsigned addr) {
    asm volatile("ldmatrix.sync.aligned.m8n8.x4.shared.b16 {%0,%1,%2,%3}, [%4];"
        : "=r"(r[0]), "=r"(r[1]), "=r"(r[2]), "=r"(r[3]) : "r"(addr));
}
__device__ __forceinline__ unsigned ex2h2(unsigned t) {
    unsigned r; asm("ex2.approx.f16x2 %0, %1;" : "=r"(r) : "r"(t)); return r;
}
__device__ __forceinline__ unsigned hfma2u(unsigned a, unsigned b, unsigned c) {
    unsigned d; asm("fma.rn.f16x2 %0, %1, %2, %3;" : "=r"(d) : "r"(a), "r"(b), "r"(c)); return d;
}

// ---------------- fp32 -> fp16 copy ----------------
__global__ __launch_bounds__(256) void conv_x(const float* __restrict__ x, fp16* __restrict__ o) {
    size_t i = ((size_t)blockIdx.x * 256 + threadIdx.x) * 4;
    float4 v = *(const float4*)(x + i);
    __half2* p = (__half2*)(o + i);
    p[0] = __floats2half2_rn(v.x, v.y);
    p[1] = __floats2half2_rn(v.z, v.w);
}

// ---------------- 4x W[k][n] fp32 -> Wt[n][k] fp16 (one launch) ----------------
__global__ __launch_bounds__(256) void conv_wt4(const float* __restrict__ W0,
                                                const float* __restrict__ W1,
                                                const float* __restrict__ W2,
                                                const float* __restrict__ W3,
                                                fp16* __restrict__ T0, fp16* __restrict__ T1,
                                                fp16* __restrict__ T2, fp16* __restrict__ T3) {
    __shared__ float tile[32][33];
    const int z = blockIdx.z;
    const float* W = (z == 0) ? W0 : (z == 1) ? W1 : (z == 2) ? W2 : W3;
    fp16* Wt = (z == 0) ? T0 : (z == 1) ? T1 : (z == 2) ? T2 : T3;
    const int bx = blockIdx.x << 5, by = blockIdx.y << 5;
    const int tx = threadIdx.x, ty = threadIdx.y;  // 32 x 8
    #pragma unroll
    for (int i = 0; i < 4; i++)
        tile[ty + 8*i][tx] = W[(size_t)(by + ty + 8*i) * DD + bx + tx];
    __syncthreads();
    #pragma unroll
    for (int i = 0; i < 4; i++)
        Wt[(size_t)(bx + ty + 8*i) * DD + by + tx] = __float2half(tile[tx][ty + 8*i]);
}

// ---------------- fp16 mma.sync GEMM body (f16 accumulate), 3-stage cp.async ----------------
// C = A[m][k] * Bt[n][k]^T + bias. Tile 128x128, k-chunk 32.
// mode 0: fp16 -> [b,h,s,d]; mode 2: fp16 -> [b,h,d,s]; mode 1: fp32 C+resid.
#define GLD 40
#define GMB (128*GLD*2)      // bytes per matrix per stage (10240)
#define GSTB (2*GMB)         // per stage (A+B) 20480
__device__ __forceinline__ void gemm_body(const fp16* __restrict__ A,
                                          const fp16* __restrict__ Bt,
                                          const float* __restrict__ bias,
                                          const float* __restrict__ resid,
                                          void* __restrict__ outp, int mode,
                                          int m0, int n0, unsigned sbase) {
    const int tid = threadIdx.x;
    const int lane = tid & 31, w = tid >> 5;
    const int wm = (w >> 1) << 5;     // 4 warps in M
    const int wn = (w & 1) << 6;      // 2 warps in N
    const int g = lane >> 2, tig = lane & 3;
    const int lrow = lane & 15, lkh = (lane >> 4) << 3;

    const int crow = tid >> 1, cch = (tid & 1) << 4;
    const fp16* gA = A  + (size_t)(m0 + crow) * DD + cch;
    const fp16* gB = Bt + (size_t)(n0 + crow) * DD + cch;
    const unsigned sA = sbase + (crow * GLD + cch) * 2;
    const unsigned sB = sA + GMB;

    unsigned aoff[2], boff[4];
    #pragma unroll
    for (int mi = 0; mi < 2; mi++)
        aoff[mi] = sbase + ((wm + (mi<<4) + lrow) * GLD + lkh) * 2;
    #pragma unroll
    for (int jj = 0; jj < 4; jj++)
        boff[jj] = sbase + GMB + ((wn + (jj<<4) + lrow) * GLD + lkh) * 2;

    unsigned acc[2][8][2];    // packed f16x2 accumulators
    #pragma unroll
    for (int mi = 0; mi < 2; mi++)
        #pragma unroll
        for (int j = 0; j < 8; j++) { acc[mi][j][0] = 0u; acc[mi][j][1] = 0u; }

    #pragma unroll
    for (int p = 0; p < 2; p++) {
        cp16(sA + p*GSTB,      gA + p*32);
        cp16(sA + p*GSTB + 16, gA + p*32 + 8);
        cp16(sB + p*GSTB,      gB + p*32);
        cp16(sB + p*GSTB + 16, gB + p*32 + 8);
        cp_commit();
    }

    for (int it = 0; it < 32; it++) {
        if (it == 31) cp_wait<0>(); else cp_wait<1>();
        __syncthreads();
        const int nit = it + 2;
        if (nit < 32) {
            const unsigned ns = (unsigned)(nit % 3) * GSTB;
            cp16(sA + ns,      gA + nit*32);
            cp16(sA + ns + 16, gA + nit*32 + 8);
            cp16(sB + ns,      gB + nit*32);
            cp16(sB + ns + 16, gB + nit*32 + 8);
            cp_commit();
        }
        const unsigned sb = (unsigned)(it % 3) * GSTB;
        #pragma unroll
        for (int ks = 0; ks < 2; ks++) {
            unsigned a0[4], a1[4];
            ldm4(a0, aoff[0] + sb + ks*32);
            ldm4(a1, aoff[1] + sb + ks*32);
            #pragma unroll
            for (int jj = 0; jj < 4; jj++) {
                unsigned b[4];
                ldm4(b, boff[jj] + sb + ks*32);
                mma16816hh(acc[0][2*jj],   a0, b[0], b[2]);
                mma16816hh(acc[0][2*jj+1], a0, b[1], b[3]);
                mma16816hh(acc[1][2*jj],   a1, b[0], b[2]);
                mma16816hh(acc[1][2*jj+1], a1, b[1], b[3]);
            }
        }
    }

    #pragma unroll
    for (int mi = 0; mi < 2; mi++) {
        #pragma unroll
        for (int j = 0; j < 8; j++) {
            const int r0 = m0 + wm + (mi<<4) + g;
            const int c0 = n0 + wn + (j<<3) + (tig<<1);
            const float bs0 = bias[c0], bs1 = bias[c0+1];
            float2 va = __half22float2(*(__half2*)&acc[mi][j][0]);
            float2 vb = __half22float2(*(__half2*)&acc[mi][j][1]);
            float v00 = va.x + bs0, v01 = va.y + bs1;
            float v10 = vb.x + bs0, v11 = vb.y + bs1;
            if (mode == 1) {
                float* y = (float*)outp;
                float2 ra = *(const float2*)(resid + (size_t)r0 * DD + c0);
                float2 rb = *(const float2*)(resid + (size_t)(r0+8) * DD + c0);
                *(float2*)(y + (size_t)r0 * DD + c0)     = make_float2(v00 + ra.x, v01 + ra.y);
                *(float2*)(y + (size_t)(r0+8) * DD + c0) = make_float2(v10 + rb.x, v11 + rb.y);
            } else {
                fp16* o = (fp16*)outp;
                const int h_ = c0 >> 6, d_ = c0 & 63;
                const int b0_ = r0 >> 11, s0_ = r0 & 2047;
                const int b1_ = (r0+8) >> 11, s1_ = (r0+8) & 2047;
                if (mode == 0) {
                    *(__half2*)(o + ((((size_t)b0_*HH + h_)*SS + s0_) << 6) + d_) =
                        __floats2half2_rn(v00, v01);
                    *(__half2*)(o + ((((size_t)b1_*HH + h_)*SS + s1_) << 6) + d_) =
                        __floats2half2_rn(v10, v11);
                } else {  // mode 2: fp16 [b,h,d,s]
                    fp16* p0 = o + (((size_t)b0_*HH + h_)*DHH + d_) * SS + s0_;
                    fp16* p1 = o + (((size_t)b1_*HH + h_)*DHH + d_) * SS + s1_;
                    p0[0]  = __float2half(v00);
                    p0[SS] = __float2half(v01);
                    p1[0]  = __float2half(v10);
                    p1[SS] = __float2half(v11);
                }
            }
        }
    }
}

// fused Q/K/V projection: grid.x = 3 segments x 8 n-tiles
__global__ __launch_bounds__(256) void gemm_qkv(const fp16* __restrict__ A,
                                                const fp16* __restrict__ wq,
                                                const fp16* __restrict__ wk,
                                                const fp16* __restrict__ wv,
                                                const float* __restrict__ bq,
                                                const float* __restrict__ bk,
                                                const float* __restrict__ bv,
                                                fp16* __restrict__ qo,
                                                fp16* __restrict__ ko,
                                                fp16* __restrict__ vo) {
    extern __shared__ char dyn[];
    const unsigned sbase = (unsigned)__cvta_generic_to_shared(dyn);
    const int seg = blockIdx.x >> 3;
    const int n0 = (blockIdx.x & 7) << 7;
    const fp16*  Bt   = (seg == 0) ? wq : (seg == 1) ? wk : wv;
    const float* bias = (seg == 0) ? bq : (seg == 1) ? bk : bv;
    void* outp        = (seg == 0) ? (void*)qo : (seg == 1) ? (void*)ko : (void*)vo;
    const int mode    = (seg == 2) ? 2 : 0;
    gemm_body(A, Bt, bias, nullptr, outp, mode, blockIdx.y << 7, n0, sbase);
}

// output projection + residual (fp32 y)
__global__ __launch_bounds__(256) void gemm_o(const fp16* __restrict__ A,
                                              const fp16* __restrict__ Bt,
                                              const float* __restrict__ bias,
                                              const float* __restrict__ resid,
                                              float* __restrict__ y) {
    extern __shared__ char dyn[];
    const unsigned sbase = (unsigned)__cvta_generic_to_shared(dyn);
    gemm_body(A, Bt, bias, resid, (void*)y, 1, blockIdx.y << 7, blockIdx.x << 7, sbase);
}

// ---------------- flash attention: all-fp16 MMA, HFMA2+ex2 softmax ----------------
#define LDK 72
#define AMB (64*LDK*2)          // 9216 bytes per matrix per stage
#define ASTB (2*AMB)            // 18432 per stage (K+V)
#define AMS (3*ASTB)            // mask offset 55296 (half mask: 4KB)
__global__ __launch_bounds__(256) void attn_mma(const float* __restrict__ mask,
                                                fp16* __restrict__ ctx) {
    extern __shared__ char dyn[];
    const unsigned sbase = (unsigned)__cvta_generic_to_shared(dyn);
    fp16* Msh = (fp16*)(dyn + AMS);
    const int bh = blockIdx.x, qt = blockIdx.y;
    const int b_ = bh >> 4, h_ = bh & 15;
    const int tid = threadIdx.x, lane = tid & 31, w = tid >> 5;
    const int g = lane >> 2, tig = lane & 3;
    const int lrow = lane & 15, lkh = (lane >> 4) << 3;
    const fp16* qg = g_q  + (size_t)bh * SS * DHH;
    const fp16* kg = g_k  + (size_t)bh * SS * DHH;
    const fp16* vg = g_vt + (size_t)bh * DHH * SS;

    const float LOG2E = 1.4426950408889634f;
    for (int i = tid; i < SS; i += 256)
        Msh[i] = __float2half(mask[(size_t)b_ * SS + i] * LOG2E);

    // Q a-fragments from global (warp: rows qrow..qrow+15, all 64 dh)
    unsigned qa[4][4];
    const int qrow = (qt << 7) + (w << 4);
    #pragma unroll
    for (int kk = 0; kk < 4; kk++) {
        const fp16* qp = qg + (size_t)(qrow + g) * 64 + (kk<<4) + (tig<<1);
        qa[kk][0] = *(const unsigned*)qp;
        qa[kk][1] = *(const unsigned*)(qp + 8*64);
        qa[kk][2] = *(const unsigned*)(qp + 8);
        qa[kk][3] = *(const unsigned*)(qp + 8*64 + 8);
    }

    // cp.async mapping: row = tid>>2 (0..63), chunk = (tid&3)*16 elems (2 x cp16)
    const int crow = tid >> 2, cch = (tid & 3) << 4;
    const unsigned sK = sbase + (crow * LDK + cch) * 2;
    const unsigned sV = sK + AMB;
    const fp16* gK = kg + (size_t)crow * 64 + cch;           // + kt*64*64
    const fp16* gV = vg + (size_t)crow * SS + cch;           // + kt*64

    unsigned noff[4];
    #pragma unroll
    for (int jj = 0; jj < 4; jj++)
        noff[jj] = (((jj<<4) + lrow) * LDK + lkh) * 2;

    // fp16 ones B-fragment: only n-column 0 is 1.0 (lanes g==0)
    const unsigned onesh = (g == 0) ? 0x3C003C00u : 0u;
    const unsigned SC2 = 0x31C631C6u;   // half2(0.125*log2(e)) = half2(0.180337)

    unsigned opk[8][2];                 // packed fp16 O accumulators
    #pragma unroll
    for (int j = 0; j < 8; j++) { opk[j][0] = 0u; opk[j][1] = 0u; }
    float csA[4] = {0.f,0.f,0.f,0.f};   // fp32 row-sum accumulators (alternating)
    float csB[4] = {0.f,0.f,0.f,0.f};

    // prologue: key tiles 0,1
    #pragma unroll
    for (int p = 0; p < 2; p++) {
        cp16(sK + p*ASTB,      gK + (size_t)p*64*64);
        cp16(sK + p*ASTB + 16, gK + (size_t)p*64*64 + 8);
        cp16(sV + p*ASTB,      gV + p*64);
        cp16(sV + p*ASTB + 16, gV + p*64 + 8);
        cp_commit();
    }

    for (int kt = 0; kt < 32; kt++) {
        if (kt == 31) cp_wait<0>(); else cp_wait<1>();
        __syncthreads();
        const int nkt = kt + 2;
        if (nkt < 32) {
            const unsigned ns = (unsigned)(nkt % 3) * ASTB;
            cp16(sK + ns,      gK + (size_t)nkt*64*64);
            cp16(sK + ns + 16, gK + (size_t)nkt*64*64 + 8);
            cp16(sV + ns,      gV + nkt*64);
            cp16(sV + ns + 16, gV + nkt*64 + 8);
            cp_commit();
        }
        const unsigned sb = (unsigned)(kt % 3) * ASTB;
        const unsigned kbase = sbase + sb;
        const unsigned vbase = kbase + AMB;

        // S = Q @ K^T  (fp16 acc; packed pairs are already PV A-frag layout)
        unsigned cpk[8][2];
        #pragma unroll
        for (int j = 0; j < 8; j++) { cpk[j][0] = 0u; cpk[j][1] = 0u; }
        #pragma unroll
        for (int kk = 0; kk < 4; kk++) {
            #pragma unroll
            for (int jj = 0; jj < 4; jj++) {
                unsigned b[4];
                ldm4(b, kbase + noff[jj] + kk*32);
                mma16816hh(cpk[2*jj],   qa[kk], b[0], b[2]);
                mma16816hh(cpk[2*jj+1], qa[kk], b[1], b[3]);
            }
        }

        // P = ex2(S*SC + mask), all in packed fp16
        const int kb = kt << 6;
        unsigned pb[4][4];
        #pragma unroll
        for (int kk = 0; kk < 4; kk++) {
            const unsigned mk0 = *(const unsigned*)(Msh + kb + (kk<<4) + (tig<<1));
            const unsigned mk1 = *(const unsigned*)(Msh + kb + (kk<<4) + 8 + (tig<<1));
            pb[kk][0] = ex2h2(hfma2u(cpk[2*kk][0],   SC2, mk0));
            pb[kk][1] = ex2h2(hfma2u(cpk[2*kk][1],   SC2, mk0));
            pb[kk][2] = ex2h2(hfma2u(cpk[2*kk+1][0], SC2, mk1));
            pb[kk][3] = ex2h2(hfma2u(cpk[2*kk+1][1], SC2, mk1));
        }

        // row sums via ones-column fp16->fp32 MMA (2 independent accumulators)
        mma16816h(csA, pb[0], onesh, onesh);
        mma16816h(csB, pb[1], onesh, onesh);
        mma16816h(csA, pb[2], onesh, onesh);
        mma16816h(csB, pb[3], onesh, onesh);

        // O += P @ V  (fp16 acc; Vs rows = dh, cols = key)
        #pragma unroll
        for (int kk = 0; kk < 4; kk++) {
            #pragma unroll
            for (int jj = 0; jj < 4; jj++) {
                unsigned b[4];
                ldm4(b, vbase + noff[jj] + kk*32);
                mma16816hh(opk[2*jj],   pb[kk], b[0], b[2]);
                mma16816hh(opk[2*jj+1], pb[kk], b[1], b[3]);
            }
        }
    }

    // row sums sit in col 0 (tig==0 lanes): regs 0 (row g) and 2 (row g+8)
    const int qlane = lane & 28;
    const float s0 = __shfl_sync(0xffffffffu, csA[0] + csB[0], qlane);
    const float s1 = __shfl_sync(0xffffffffu, csA[2] + csB[2], qlane);
    const float inv0 = 1.0f / s0, inv1 = 1.0f / s1;
    const int r0 = qrow + g;
    #pragma unroll
    for (int j = 0; j < 8; j++) {
        const int col = (h_ << 6) + (j<<3) + (tig<<1);
        float2 f0 = __half22float2(*(__half2*)&opk[j][0]);
        float2 f1 = __half22float2(*(__half2*)&opk[j][1]);
        *(__half2*)(ctx + ((size_t)b_*SS + r0) * DD + col) =
            __floats2half2_rn(f0.x*inv0, f0.y*inv0);
        *(__half2*)(ctx + ((size_t)b_*SS + r0 + 8) * DD + col) =
            __floats2half2_rn(f1.x*inv1, f1.y*inv1);
    }
}

// ---------------- LayerNorm (fp32) ----------------
__global__ __launch_bounds__(256) void ln_kernel(const float* __restrict__ y,
                                                 const float* __restrict__ gamma,
                                                 const float* __restrict__ beta,
                                                 float* __restrict__ out) {
    const int row = blockIdx.x;
    const int tid = threadIdx.x;
    const float* yr = y + (size_t)row * DD;
    const int c = tid << 2;
    float4 v = *(const float4*)(yr + c);
    float s  = v.x + v.y + v.z + v.w;
    float ss = v.x*v.x + v.y*v.y + v.z*v.z + v.w*v.w;
    #pragma unroll
    for (int off = 16; off > 0; off >>= 1) {
        s  += __shfl_xor_sync(0xffffffffu, s,  off);
        ss += __shfl_xor_sync(0xffffffffu, ss, off);
    }
    __shared__ float rs[8], rss[8];
    if ((tid & 31) == 0) { rs[tid >> 5] = s; rss[tid >> 5] = ss; }
    __syncthreads();
    if (tid < 32) {
        float a = (tid < 8) ? rs[tid] : 0.f;
        float b = (tid < 8) ? rss[tid] : 0.f;
        #pragma unroll
        for (int off = 4; off > 0; off >>= 1) {
            a += __shfl_xor_sync(0xffffffffu, a, off);
            b += __shfl_xor_sync(0xffffffffu, b, off);
        }
        if (tid == 0) { rs[0] = a; rss[0] = b; }
    }
    __syncthreads();
    const float mu  = rs[0] * (1.0f / 1024.0f);
    const float var = rss[0] * (1.0f / 1024.0f) - mu * mu;
    const float r = rsqrtf(var + 1e-12f);
    float4 gv = *(const float4*)(gamma + c);
    float4 bt = *(const float4*)(beta + c);
    float4 ov;
    ov.x = (v.x - mu) * r * gv.x + bt.x;
    ov.y = (v.y - mu) * r * gv.y + bt.y;
    ov.z = (v.z - mu) * r * gv.z + bt.z;
    ov.w = (v.w - mu) * r * gv.w + bt.w;
    *(float4*)(out + (size_t)row * DD + c) = ov;
}

extern "C" void kernel_launch(void* const* d_in, const int* in_sizes, int n_in,
                              void* d_out, int out_size) {
    (void)in_sizes; (void)n_in; (void)out_size;
    const float* x     = (const float*)d_in[0];
    const float* mask  = (const float*)d_in[1];
    const float* Wq    = (const float*)d_in[2];
    const float* bq    = (const float*)d_in[3];
    const float* Wk    = (const float*)d_in[4];
    const float* bk    = (const float*)d_in[5];
    const float* Wv    = (const float*)d_in[6];
    const float* bv    = (const float*)d_in[7];
    const float* Wo    = (const float*)d_in[8];
    const float* bo    = (const float*)d_in[9];
    const float* gamma = (const float*)d_in[10];
    const float* beta  = (const float*)d_in[11];
    float* out = (float*)d_out;

    fp16 *xb, *wq, *wk, *wv, *wo, *qp, *kp, *vtp, *ctxp;
    float *yp;
    cudaGetSymbolAddress((void**)&xb,   g_xb);
    cudaGetSymbolAddress((void**)&wq,   g_wq);
    cudaGetSymbolAddress((void**)&wk,   g_wk);
    cudaGetSymbolAddress((void**)&wv,   g_wv);
    cudaGetSymbolAddress((void**)&wo,   g_wo);
    cudaGetSymbolAddress((void**)&qp,   g_q);
    cudaGetSymbolAddress((void**)&kp,   g_k);
    cudaGetSymbolAddress((void**)&vtp,  g_vt);
    cudaGetSymbolAddress((void**)&ctxp, g_ctx);
    cudaGetSymbolAddress((void**)&yp,   g_y);

    const int gemm_smem = 3 * GSTB;               // 61440
    const int attn_smem = AMS + SS * 2;           // 59392
    cudaFuncSetAttribute(gemm_qkv, cudaFuncAttributeMaxDynamicSharedMemorySize, gemm_smem);
    cudaFuncSetAttribute(gemm_o,   cudaFuncAttributeMaxDynamicSharedMemorySize, gemm_smem);
    cudaFuncSetAttribute(attn_mma, cudaFuncAttributeMaxDynamicSharedMemorySize, attn_smem);

    conv_x<<<(int)(((size_t)MM*DD)/1024), 256>>>(x, xb);
    conv_wt4<<<dim3(32, 32, 4), dim3(32, 8)>>>(Wq, Wk, Wv, Wo, wq, wk, wv, wo);

    gemm_qkv<<<dim3(24, MM/128), 256, gemm_smem>>>(xb, wq, wk, wv, bq, bk, bv, qp, kp, vtp);

    attn_mma<<<dim3(64, 16), 256, attn_smem>>>(mask, ctxp);

    gemm_o<<<dim3(DD/128, MM/128), 256, gemm_smem>>>(ctxp, wo, bo, x, yp);
    ln_kernel<<<MM, 256>>>(yp, gamma, beta, out);
}

// round 13
// speedup vs baseline: 1.9765x; 1.0581x over previous
#include <cuda_runtime.h>
#include <cuda_bf16.h>
#include <cuda_fp16.h>
#include <cstdint>
#include <math.h>

#define BB 4
#define SS 2048
#define DD 1024
#define HH 16
#define DHH 64
#define MM (BB*SS)

typedef __half fp16;

// ---------------- device scratch (allocation-free rule) ----------------
__device__ fp16  g_xb[(size_t)MM*DD];      // x in fp16 [m][k]
__device__ fp16  g_wq[DD*DD];              // W^T fp16 [n][k]
__device__ fp16  g_wk[DD*DD];
__device__ fp16  g_wv[DD*DD];
__device__ fp16  g_wo[DD*DD];
__device__ fp16  g_q [(size_t)MM*DD];      // [b,h,s,d]
__device__ fp16  g_k [(size_t)MM*DD];      // [b,h,s,d]
__device__ fp16  g_vt[(size_t)MM*DD];      // [b,h,d,s]  (transposed for PV)
__device__ fp16  g_ctx[(size_t)MM*DD];     // [m][n]
__device__ float g_y [(size_t)MM*DD];      // pre-LN fp32

// ---------------- helpers ----------------
__device__ __forceinline__ void cp16(unsigned dst, const void* src) {
    asm volatile("cp.async.cg.shared.global [%0], [%1], 16;\n" :: "r"(dst), "l"(src));
}
__device__ __forceinline__ void cp_commit() { asm volatile("cp.async.commit_group;\n"); }
template<int N> __device__ __forceinline__ void cp_wait() {
    asm volatile("cp.async.wait_group %0;\n" :: "n"(N));
}
// fp16 x fp16 -> fp16 accumulate
__device__ __forceinline__ void mma16816hh(unsigned* d, const unsigned* a, unsigned b0, unsigned b1) {
    asm volatile("mma.sync.aligned.m16n8k16.row.col.f16.f16.f16.f16 "
        "{%0,%1}, {%2,%3,%4,%5}, {%6,%7}, {%0,%1};"
        : "+r"(d[0]), "+r"(d[1])
        : "r"(a[0]), "r"(a[1]), "r"(a[2]), "r"(a[3]), "r"(b0), "r"(b1));
}
// fp16 x fp16 -> fp32 accumulate (row sums only)
__device__ __forceinline__ void mma16816h(float* d, const unsigned* a, unsigned b0, unsigned b1) {
    asm volatile("mma.sync.aligned.m16n8k16.row.col.f32.f16.f16.f32 "
        "{%0,%1,%2,%3}, {%4,%5,%6,%7}, {%8,%9}, {%0,%1,%2,%3};"
        : "+f"(d[0]), "+f"(d[1]), "+f"(d[2]), "+f"(d[3])
        : "r"(a[0]), "r"(a[1]), "r"(a[2]), "r"(a[3]), "r"(b0), "r"(b1));
}
__device__ __forceinline__ void ldm4(unsigned* r, unsigned addr) {
    asm volatile("ldmatrix.sync.aligned.m8n8.x4.shared.b16 {%0,%1,%2,%3}, [%4];"
        : "=r"(r[0]), "=r"(r[1]), "=r"(r[2]), "=r"(r[3]) : "r"(addr));
}
__device__ __forceinline__ unsigned ex2h2(unsigned t) {
    unsigned r; asm("ex2.approx.f16x2 %0, %1;" : "=r"(r) : "r"(t)); return r;
}
__device__ __forceinline__ unsigned hfma2u(unsigned a, unsigned b, unsigned c) {
    unsigned d; asm("fma.rn.f16x2 %0, %1, %2, %3;" : "=r"(d) : "r"(a), "r"(b), "r"(c)); return d;
}

// ---------------- fp32 -> fp16 copy ----------------
__global__ __launch_bounds__(256) void conv_x(const float* __restrict__ x, fp16* __restrict__ o) {
    size_t i = ((size_t)blockIdx.x * 256 + threadIdx.x) * 4;
    float4 v = *(const float4*)(x + i);
    __half2* p = (__half2*)(o + i);
    p[0] = __floats2half2_rn(v.x, v.y);
    p[1] = __floats2half2_rn(v.z, v.w);
}

// ---------------- 4x W[k][n] fp32 -> Wt[n][k] fp16 (one launch) ----------------
__global__ __launch_bounds__(256) void conv_wt4(const float* __restrict__ W0,
                                                const float* __restrict__ W1,
                                                const float* __restrict__ W2,
                                                const float* __restrict__ W3,
                                                fp16* __restrict__ T0, fp16* __restrict__ T1,
                                                fp16* __restrict__ T2, fp16* __restrict__ T3) {
    __shared__ float tile[32][33];
    const int z = blockIdx.z;
    const float* W = (z == 0) ? W0 : (z == 1) ? W1 : (z == 2) ? W2 : W3;
    fp16* Wt = (z == 0) ? T0 : (z == 1) ? T1 : (z == 2) ? T2 : T3;
    const int bx = blockIdx.x << 5, by = blockIdx.y << 5;
    const int tx = threadIdx.x, ty = threadIdx.y;  // 32 x 8
    #pragma unroll
    for (int i = 0; i < 4; i++)
        tile[ty + 8*i][tx] = W[(size_t)(by + ty + 8*i) * DD + bx + tx];
    __syncthreads();
    #pragma unroll
    for (int i = 0; i < 4; i++)
        Wt[(size_t)(bx + ty + 8*i) * DD + by + tx] = __float2half(tile[tx][ty + 8*i]);
}

// ---------------- fp16 mma.sync GEMM body (f16 accumulate), 3-stage cp.async ----------------
// C = A[m][k] * Bt[n][k]^T + bias. Tile 128x128, k-chunk 32.
// mode 0: fp16 -> [b,h,s,d]; mode 2: fp16 -> [b,h,d,s]; mode 1: fp32 C+resid.
#define GLD 40
#define GMB (128*GLD*2)      // bytes per matrix per stage (10240)
#define GSTB (2*GMB)         // per stage (A+B) 20480
__device__ __forceinline__ void gemm_body(const fp16* __restrict__ A,
                                          const fp16* __restrict__ Bt,
                                          const float* __restrict__ bias,
                                          const float* __restrict__ resid,
                                          void* __restrict__ outp, int mode,
                                          int m0, int n0, unsigned sbase) {
    const int tid = threadIdx.x;
    const int lane = tid & 31, w = tid >> 5;
    const int wm = (w >> 1) << 5;     // 4 warps in M
    const int wn = (w & 1) << 6;      // 2 warps in N
    const int g = lane >> 2, tig = lane & 3;
    const int lrow = lane & 15, lkh = (lane >> 4) << 3;

    const int crow = tid >> 1, cch = (tid & 1) << 4;
    const fp16* gA = A  + (size_t)(m0 + crow) * DD + cch;
    const fp16* gB = Bt + (size_t)(n0 + crow) * DD + cch;
    const unsigned sA = sbase + (crow * GLD + cch) * 2;
    const unsigned sB = sA + GMB;

    unsigned aoff[2], boff[4];
    #pragma unroll
    for (int mi = 0; mi < 2; mi++)
        aoff[mi] = sbase + ((wm + (mi<<4) + lrow) * GLD + lkh) * 2;
    #pragma unroll
    for (int jj = 0; jj < 4; jj++)
        boff[jj] = sbase + GMB + ((wn + (jj<<4) + lrow) * GLD + lkh) * 2;

    unsigned acc[2][8][2];    // packed f16x2 accumulators
    #pragma unroll
    for (int mi = 0; mi < 2; mi++)
        #pragma unroll
        for (int j = 0; j < 8; j++) { acc[mi][j][0] = 0u; acc[mi][j][1] = 0u; }

    #pragma unroll
    for (int p = 0; p < 2; p++) {
        cp16(sA + p*GSTB,      gA + p*32);
        cp16(sA + p*GSTB + 16, gA + p*32 + 8);
        cp16(sB + p*GSTB,      gB + p*32);
        cp16(sB + p*GSTB + 16, gB + p*32 + 8);
        cp_commit();
    }

    for (int it = 0; it < 32; it++) {
        if (it == 31) cp_wait<0>(); else cp_wait<1>();
        __syncthreads();
        const int nit = it + 2;
        if (nit < 32) {
            const unsigned ns = (unsigned)(nit % 3) * GSTB;
            cp16(sA + ns,      gA + nit*32);
            cp16(sA + ns + 16, gA + nit*32 + 8);
            cp16(sB + ns,      gB + nit*32);
            cp16(sB + ns + 16, gB + nit*32 + 8);
            cp_commit();
        }
        const unsigned sb = (unsigned)(it % 3) * GSTB;
        #pragma unroll
        for (int ks = 0; ks < 2; ks++) {
            unsigned a0[4], a1[4];
            ldm4(a0, aoff[0] + sb + ks*32);
            ldm4(a1, aoff[1] + sb + ks*32);
            #pragma unroll
            for (int jj = 0; jj < 4; jj++) {
                unsigned b[4];
                ldm4(b, boff[jj] + sb + ks*32);
                mma16816hh(acc[0][2*jj],   a0, b[0], b[2]);
                mma16816hh(acc[0][2*jj+1], a0, b[1], b[3]);
                mma16816hh(acc[1][2*jj],   a1, b[0], b[2]);
                mma16816hh(acc[1][2*jj+1], a1, b[1], b[3]);
            }
        }
    }

    #pragma unroll
    for (int mi = 0; mi < 2; mi++) {
        #pragma unroll
        for (int j = 0; j < 8; j++) {
            const int r0 = m0 + wm + (mi<<4) + g;
            const int c0 = n0 + wn + (j<<3) + (tig<<1);
            const float bs0 = bias[c0], bs1 = bias[c0+1];
            float2 va = __half22float2(*(__half2*)&acc[mi][j][0]);
            float2 vb = __half22float2(*(__half2*)&acc[mi][j][1]);
            float v00 = va.x + bs0, v01 = va.y + bs1;
            float v10 = vb.x + bs0, v11 = vb.y + bs1;
            if (mode == 1) {
                float* y = (float*)outp;
                float2 ra = *(const float2*)(resid + (size_t)r0 * DD + c0);
                float2 rb = *(const float2*)(resid + (size_t)(r0+8) * DD + c0);
                *(float2*)(y + (size_t)r0 * DD + c0)     = make_float2(v00 + ra.x, v01 + ra.y);
                *(float2*)(y + (size_t)(r0+8) * DD + c0) = make_float2(v10 + rb.x, v11 + rb.y);
            } else {
                fp16* o = (fp16*)outp;
                const int h_ = c0 >> 6, d_ = c0 & 63;
                const int b0_ = r0 >> 11, s0_ = r0 & 2047;
                const int b1_ = (r0+8) >> 11, s1_ = (r0+8) & 2047;
                if (mode == 0) {
                    *(__half2*)(o + ((((size_t)b0_*HH + h_)*SS + s0_) << 6) + d_) =
                        __floats2half2_rn(v00, v01);
                    *(__half2*)(o + ((((size_t)b1_*HH + h_)*SS + s1_) << 6) + d_) =
                        __floats2half2_rn(v10, v11);
                } else {  // mode 2: fp16 [b,h,d,s]
                    fp16* p0 = o + (((size_t)b0_*HH + h_)*DHH + d_) * SS + s0_;
                    fp16* p1 = o + (((size_t)b1_*HH + h_)*DHH + d_) * SS + s1_;
                    p0[0]  = __float2half(v00);
                    p0[SS] = __float2half(v01);
                    p1[0]  = __float2half(v10);
                    p1[SS] = __float2half(v11);
                }
            }
        }
    }
}

// fused Q/K/V projection: grid.x = 3 segments x 8 n-tiles
__global__ __launch_bounds__(256, 3) void gemm_qkv(const fp16* __restrict__ A,
                                                   const fp16* __restrict__ wq,
                                                   const fp16* __restrict__ wk,
                                                   const fp16* __restrict__ wv,
                                                   const float* __restrict__ bq,
                                                   const float* __restrict__ bk,
                                                   const float* __restrict__ bv,
                                                   fp16* __restrict__ qo,
                                                   fp16* __restrict__ ko,
                                                   fp16* __restrict__ vo) {
    extern __shared__ char dyn[];
    const unsigned sbase = (unsigned)__cvta_generic_to_shared(dyn);
    const int seg = blockIdx.x >> 3;
    const int n0 = (blockIdx.x & 7) << 7;
    const fp16*  Bt   = (seg == 0) ? wq : (seg == 1) ? wk : wv;
    const float* bias = (seg == 0) ? bq : (seg == 1) ? bk : bv;
    void* outp        = (seg == 0) ? (void*)qo : (seg == 1) ? (void*)ko : (void*)vo;
    const int mode    = (seg == 2) ? 2 : 0;
    gemm_body(A, Bt, bias, nullptr, outp, mode, blockIdx.y << 7, n0, sbase);
}

// output projection + residual (fp32 y)
__global__ __launch_bounds__(256, 3) void gemm_o(const fp16* __restrict__ A,
                                                 const fp16* __restrict__ Bt,
                                                 const float* __restrict__ bias,
                                                 const float* __restrict__ resid,
                                                 float* __restrict__ y) {
    extern __shared__ char dyn[];
    const unsigned sbase = (unsigned)__cvta_generic_to_shared(dyn);
    gemm_body(A, Bt, bias, resid, (void*)y, 1, blockIdx.y << 7, blockIdx.x << 7, sbase);
}

// ---------------- flash attention: all-fp16 MMA, HFMA2+ex2 softmax ----------------
#define LDK 72
#define AMB (64*LDK*2)          // 9216 bytes per matrix per stage
#define ASTB (2*AMB)            // 18432 per stage (K+V)
#define AMS (3*ASTB)            // mask offset 55296 (half mask: 4KB)
__global__ __launch_bounds__(256, 3) void attn_mma(const float* __restrict__ mask,
                                                   fp16* __restrict__ ctx) {
    extern __shared__ char dyn[];
    const unsigned sbase = (unsigned)__cvta_generic_to_shared(dyn);
    fp16* Msh = (fp16*)(dyn + AMS);
    const int bh = blockIdx.x, qt = blockIdx.y;
    const int b_ = bh >> 4, h_ = bh & 15;
    const int tid = threadIdx.x, lane = tid & 31, w = tid >> 5;
    const int g = lane >> 2, tig = lane & 3;
    const int lrow = lane & 15, lkh = (lane >> 4) << 3;
    const fp16* qg = g_q  + (size_t)bh * SS * DHH;
    const fp16* kg = g_k  + (size_t)bh * SS * DHH;
    const fp16* vg = g_vt + (size_t)bh * DHH * SS;

    const float LOG2E = 1.4426950408889634f;
    for (int i = tid; i < SS; i += 256)
        Msh[i] = __float2half(mask[(size_t)b_ * SS + i] * LOG2E);

    // Q a-fragments from global (warp: rows qrow..qrow+15, all 64 dh)
    unsigned qa[4][4];
    const int qrow = (qt << 7) + (w << 4);
    #pragma unroll
    for (int kk = 0; kk < 4; kk++) {
        const fp16* qp = qg + (size_t)(qrow + g) * 64 + (kk<<4) + (tig<<1);
        qa[kk][0] = *(const unsigned*)qp;
        qa[kk][1] = *(const unsigned*)(qp + 8*64);
        qa[kk][2] = *(const unsigned*)(qp + 8);
        qa[kk][3] = *(const unsigned*)(qp + 8*64 + 8);
    }

    // cp.async mapping: row = tid>>2 (0..63), chunk = (tid&3)*16 elems (2 x cp16)
    const int crow = tid >> 2, cch = (tid & 3) << 4;
    const unsigned sK = sbase + (crow * LDK + cch) * 2;
    const unsigned sV = sK + AMB;
    const fp16* gK = kg + (size_t)crow * 64 + cch;           // + kt*64*64
    const fp16* gV = vg + (size_t)crow * SS + cch;           // + kt*64

    unsigned noff[4];
    #pragma unroll
    for (int jj = 0; jj < 4; jj++)
        noff[jj] = (((jj<<4) + lrow) * LDK + lkh) * 2;

    // fp16 ones B-fragment: only n-column 0 is 1.0 (lanes g==0)
    const unsigned onesh = (g == 0) ? 0x3C003C00u : 0u;
    const unsigned SC2 = 0x31C631C6u;   // half2(0.125*log2(e)) = half2(0.180337)

    unsigned opk[8][2];                 // packed fp16 O accumulators
    #pragma unroll
    for (int j = 0; j < 8; j++) { opk[j][0] = 0u; opk[j][1] = 0u; }
    float csA[4] = {0.f,0.f,0.f,0.f};   // fp32 row-sum accumulators (alternating)
    float csB[4] = {0.f,0.f,0.f,0.f};

    // prologue: key tiles 0,1
    #pragma unroll
    for (int p = 0; p < 2; p++) {
        cp16(sK + p*ASTB,      gK + (size_t)p*64*64);
        cp16(sK + p*ASTB + 16, gK + (size_t)p*64*64 + 8);
        cp16(sV + p*ASTB,      gV + p*64);
        cp16(sV + p*ASTB + 16, gV + p*64 + 8);
        cp_commit();
    }

    for (int kt = 0; kt < 32; kt++) {
        if (kt == 31) cp_wait<0>(); else cp_wait<1>();
        __syncthreads();
        const int nkt = kt + 2;
        if (nkt < 32) {
            const unsigned ns = (unsigned)(nkt % 3) * ASTB;
            cp16(sK + ns,      gK + (size_t)nkt*64*64);
            cp16(sK + ns + 16, gK + (size_t)nkt*64*64 + 8);
            cp16(sV + ns,      gV + nkt*64);
            cp16(sV + ns + 16, gV + nkt*64 + 8);
            cp_commit();
        }
        const unsigned sb = (unsigned)(kt % 3) * ASTB;
        const unsigned kbase = sbase + sb;
        const unsigned vbase = kbase + AMB;

        // S = Q @ K^T  (fp16 acc; packed pairs are already PV A-frag layout)
        unsigned cpk[8][2];
        #pragma unroll
        for (int j = 0; j < 8; j++) { cpk[j][0] = 0u; cpk[j][1] = 0u; }
        #pragma unroll
        for (int kk = 0; kk < 4; kk++) {
            #pragma unroll
            for (int jj = 0; jj < 4; jj++) {
                unsigned b[4];
                ldm4(b, kbase + noff[jj] + kk*32);
                mma16816hh(cpk[2*jj],   qa[kk], b[0], b[2]);
                mma16816hh(cpk[2*jj+1], qa[kk], b[1], b[3]);
            }
        }

        // P = ex2(S*SC + mask), all in packed fp16
        const int kb = kt << 6;
        unsigned pb[4][4];
        #pragma unroll
        for (int kk = 0; kk < 4; kk++) {
            const unsigned mk0 = *(const unsigned*)(Msh + kb + (kk<<4) + (tig<<1));
            const unsigned mk1 = *(const unsigned*)(Msh + kb + (kk<<4) + 8 + (tig<<1));
            pb[kk][0] = ex2h2(hfma2u(cpk[2*kk][0],   SC2, mk0));
            pb[kk][1] = ex2h2(hfma2u(cpk[2*kk][1],   SC2, mk0));
            pb[kk][2] = ex2h2(hfma2u(cpk[2*kk+1][0], SC2, mk1));
            pb[kk][3] = ex2h2(hfma2u(cpk[2*kk+1][1], SC2, mk1));
        }

        // row sums via ones-column fp16->fp32 MMA (2 independent accumulators)
        mma16816h(csA, pb[0], onesh, onesh);
        mma16816h(csB, pb[1], onesh, onesh);
        mma16816h(csA, pb[2], onesh, onesh);
        mma16816h(csB, pb[3], onesh, onesh);

        // O += P @ V  (fp16 acc; Vs rows = dh, cols = key)
        #pragma unroll
        for (int kk = 0; kk < 4; kk++) {
            #pragma unroll
            for (int jj = 0; jj < 4; jj++) {
                unsigned b[4];
                ldm4(b, vbase + noff[jj] + kk*32);
                mma16816hh(opk[2*jj],   pb[kk], b[0], b[2]);
                mma16816hh(opk[2*jj+1], pb[kk], b[1], b[3]);
            }
        }
    }

    // row sums sit in col 0 (tig==0 lanes): regs 0 (row g) and 2 (row g+8)
    const int qlane = lane & 28;
    const float s0 = __shfl_sync(0xffffffffu, csA[0] + csB[0], qlane);
    const float s1 = __shfl_sync(0xffffffffu, csA[2] + csB[2], qlane);
    const float inv0 = 1.0f / s0, inv1 = 1.0f / s1;
    const int r0 = qrow + g;
    #pragma unroll
    for (int j = 0; j < 8; j++) {
        const int col = (h_ << 6) + (j<<3) + (tig<<1);
        float2 f0 = __half22float2(*(__half2*)&opk[j][0]);
        float2 f1 = __half22float2(*(__half2*)&opk[j][1]);
        *(__half2*)(ctx + ((size_t)b_*SS + r0) * DD + col) =
            __floats2half2_rn(f0.x*inv0, f0.y*inv0);
        *(__half2*)(ctx + ((size_t)b_*SS + r0 + 8) * DD + col) =
            __floats2half2_rn(f1.x*inv1, f1.y*inv1);
    }
}

// ---------------- LayerNorm (fp32), warp-per-row: no block barriers ----------------
__global__ __launch_bounds__(256) void ln_kernel(const float* __restrict__ y,
                                                 const float* __restrict__ gamma,
                                                 const float* __restrict__ beta,
                                                 float* __restrict__ out) {
    const int wid = threadIdx.x >> 5, lane = threadIdx.x & 31;
    const int row = (blockIdx.x << 3) + wid;
    const float* yr = y + (size_t)row * DD;
    float4 v[8];
    float s = 0.f, ss = 0.f;
    #pragma unroll
    for (int i = 0; i < 8; i++) {
        v[i] = *(const float4*)(yr + ((i << 5) + lane) * 4);
        s  += v[i].x + v[i].y + v[i].z + v[i].w;
        ss += v[i].x*v[i].x + v[i].y*v[i].y + v[i].z*v[i].z + v[i].w*v[i].w;
    }
    #pragma unroll
    for (int off = 16; off > 0; off >>= 1) {
        s  += __shfl_xor_sync(0xffffffffu, s,  off);
        ss += __shfl_xor_sync(0xffffffffu, ss, off);
    }
    const float mu  = s * (1.0f / 1024.0f);
    const float var = ss * (1.0f / 1024.0f) - mu * mu;
    const float r = rsqrtf(var + 1e-12f);
    float* orow = out + (size_t)row * DD;
    #pragma unroll
    for (int i = 0; i < 8; i++) {
        const int c = ((i << 5) + lane) * 4;
        float4 gv = *(const float4*)(gamma + c);
        float4 bt = *(const float4*)(beta + c);
        float4 ov;
        ov.x = (v[i].x - mu) * r * gv.x + bt.x;
        ov.y = (v[i].y - mu) * r * gv.y + bt.y;
        ov.z = (v[i].z - mu) * r * gv.z + bt.z;
        ov.w = (v[i].w - mu) * r * gv.w + bt.w;
        *(float4*)(orow + c) = ov;
    }
}

extern "C" void kernel_launch(void* const* d_in, const int* in_sizes, int n_in,
                              void* d_out, int out_size) {
    (void)in_sizes; (void)n_in; (void)out_size;
    const float* x     = (const float*)d_in[0];
    const float* mask  = (const float*)d_in[1];
    const float* Wq    = (const float*)d_in[2];
    const float* bq    = (const float*)d_in[3];
    const float* Wk    = (const float*)d_in[4];
    const float* bk    = (const float*)d_in[5];
    const float* Wv    = (const float*)d_in[6];
    const float* bv    = (const float*)d_in[7];
    const float* Wo    = (const float*)d_in[8];
    const float* bo    = (const float*)d_in[9];
    const float* gamma = (const float*)d_in[10];
    const float* beta  = (const float*)d_in[11];
    float* out = (float*)d_out;

    fp16 *xb, *wq, *wk, *wv, *wo, *qp, *kp, *vtp, *ctxp;
    float *yp;
    cudaGetSymbolAddress((void**)&xb,   g_xb);
    cudaGetSymbolAddress((void**)&wq,   g_wq);
    cudaGetSymbolAddress((void**)&wk,   g_wk);
    cudaGetSymbolAddress((void**)&wv,   g_wv);
    cudaGetSymbolAddress((void**)&wo,   g_wo);
    cudaGetSymbolAddress((void**)&qp,   g_q);
    cudaGetSymbolAddress((void**)&kp,   g_k);
    cudaGetSymbolAddress((void**)&vtp,  g_vt);
    cudaGetSymbolAddress((void**)&ctxp, g_ctx);
    cudaGetSymbolAddress((void**)&yp,   g_y);

    const int gemm_smem = 3 * GSTB;               // 61440
    const int attn_smem = AMS + SS * 2;           // 59392
    cudaFuncSetAttribute(gemm_qkv, cudaFuncAttributeMaxDynamicSharedMemorySize, gemm_smem);
    cudaFuncSetAttribute(gemm_o,   cudaFuncAttributeMaxDynamicSharedMemorySize, gemm_smem);
    cudaFuncSetAttribute(attn_mma, cudaFuncAttributeMaxDynamicSharedMemorySize, attn_smem);

    conv_x<<<(int)(((size_t)MM*DD)/1024), 256>>>(x, xb);
    conv_wt4<<<dim3(32, 32, 4), dim3(32, 8)>>>(Wq, Wk, Wv, Wo, wq, wk, wv, wo);

    gemm_qkv<<<dim3(24, MM/128), 256, gemm_smem>>>(xb, wq, wk, wv, bq, bk, bv, qp, kp, vtp);

    attn_mma<<<dim3(64, 16), 256, attn_smem>>>(mask, ctxp);

    gemm_o<<<dim3(DD/128, MM/128), 256, gemm_smem>>>(ctxp, wo, bo, x, yp);
    ln_kernel<<<MM/8, 256>>>(yp, gamma, beta, out);
}